// round 13
// baseline (speedup 1.0000x reference)
#include <cuda_runtime.h>
#include <cuda_bf16.h>
#include <math.h>
#include <stdint.h>

#define BSZ 32
#define NXS 16384
#define IN_DIM 3
#define DIMC 64
#define NJ 16
#define MODE 128
#define RANKR 4
#define FCD 128
#define N_LAYERS 3
#define XH_SPLITS 8
#define Y_SPLITS 4
#define T_SPLITS 8

typedef unsigned short ushortx;

__device__ ushortx g_hxHIa[(size_t)BSZ*NXS*DIMC];
__device__ ushortx g_hxLOa[(size_t)BSZ*NXS*DIMC];
__device__ ushortx g_hxHIb[(size_t)BSZ*NXS*DIMC];
__device__ ushortx g_hxLOb[(size_t)BSZ*NXS*DIMC];
__device__ ushortx g_wbTHI[(size_t)MODE*NXS];
__device__ ushortx g_wbTLO[(size_t)MODE*NXS];
__device__ ushortx g_basesHI[(size_t)NXS*MODE];
__device__ ushortx g_basesLO[(size_t)NXS*MODE];
__device__ ushortx g_W1THI[FCD*DIMC];
__device__ ushortx g_W1TLO[FCD*DIMC];
__device__ ushortx g_HjHI[NJ*MODE*MODE];
__device__ ushortx g_HjLO[NJ*MODE*MODE];
__device__ ushortx g_xhHI[BSZ*DIMC*MODE];
__device__ ushortx g_xhLO[BSZ*DIMC*MODE];
__device__ ushortx g_x1THI[(size_t)BSZ*MODE*(DIMC*NJ)];
__device__ ushortx g_x1TLO[(size_t)BSZ*MODE*(DIMC*NJ)];
__device__ ushortx g_WrTTHI[DIMC*DIMC*NJ];
__device__ ushortx g_WrTTLO[DIMC*DIMC*NJ];
__device__ ushortx g_yHI[BSZ*DIMC*MODE];
__device__ ushortx g_yLO[BSZ*DIMC*MODE];
__device__ ushortx g_WcHI[DIMC*DIMC];
__device__ ushortx g_WcLO[DIMC*DIMC];
__device__ float g_xT[BSZ*IN_DIM*NXS];
__device__ float g_xhp[XH_SPLITS*BSZ*DIMC*MODE];
__device__ float g_yp [Y_SPLITS*BSZ*DIMC*MODE];
__device__ float g_Tp [T_SPLITS*BSZ*4*MODE];
__device__ float g_Wc0T[IN_DIM*DIMC];
__device__ float g_bias0[DIMC];

__device__ __forceinline__ float gelu_f(float v){
    return 0.5f * v * (1.0f + erff(v * 0.70710678118654752440f));
}
__device__ __forceinline__ void split2(float x, ushortx& hi, ushortx& lo){
    __nv_bfloat16 h = __float2bfloat16(x);
    hi = __bfloat16_as_ushort(h);
    lo = __bfloat16_as_ushort(__float2bfloat16(x - __bfloat162float(h)));
}
__device__ __forceinline__ unsigned pk_split(float x){
    ushortx hi, lo; split2(x, hi, lo);
    return ((unsigned)hi << 16) | (unsigned)lo;
}
#define MMA(c,a,b) asm volatile( \
    "mma.sync.aligned.m16n8k16.row.col.f32.bf16.bf16.f32 " \
    "{%0,%1,%2,%3}, {%4,%5,%6,%7}, {%8,%9}, {%0,%1,%2,%3};" \
    : "+f"((c)[0]), "+f"((c)[1]), "+f"((c)[2]), "+f"((c)[3]) \
    : "r"((a)[0]), "r"((a)[1]), "r"((a)[2]), "r"((a)[3]), "r"((b)[0]), "r"((b)[1]))
#define LDSM4(f,addr) asm volatile( \
    "ldmatrix.sync.aligned.m8n8.x4.shared.b16 {%0,%1,%2,%3}, [%4];" \
    : "=r"((f)[0]), "=r"((f)[1]), "=r"((f)[2]), "=r"((f)[3]) : "r"(addr))
#define LDSM4T(f,addr) asm volatile( \
    "ldmatrix.sync.aligned.m8n8.x4.trans.shared.b16 {%0,%1,%2,%3}, [%4];" \
    : "=r"((f)[0]), "=r"((f)[1]), "=r"((f)[2]), "=r"((f)[3]) : "r"(addr))
#define CPA(dst,src) asm volatile("cp.async.cg.shared.global [%0], [%1], 16;" :: "r"(dst), "l"(src))
#define CPC() asm volatile("cp.async.commit_group;" ::: "memory")
#define CPW0() asm volatile("cp.async.wait_group 0;" ::: "memory")

// ---------------- prep ----------------
__global__ void k_xT(const float* __restrict__ x){
    int i = blockIdx.x * 256 + threadIdx.x;
    int d = i % 3, t = i / 3;
    g_xT[((size_t)(t >> 14)*IN_DIM + d)*NXS + (t & (NXS-1))] = x[i];
}
__global__ void k_basesP(const float* __restrict__ bases){
    int i = blockIdx.x * 256 + threadIdx.x;
    split2(bases[i], g_basesHI[i], g_basesLO[i]);
}
__global__ void k_wbTP(const float* __restrict__ wb){
    __shared__ float t[32][33];
    int x0 = blockIdx.x * 32, k0 = blockIdx.y * 32;
    for (int i = threadIdx.y; i < 32; i += 8)
        t[i][threadIdx.x] = wb[(size_t)(x0 + i)*MODE + k0 + threadIdx.x];
    __syncthreads();
    for (int i = threadIdx.y; i < 32; i += 8){
        size_t o = (size_t)(k0 + i)*NXS + x0 + threadIdx.x;
        split2(t[threadIdx.x][i], g_wbTHI[o], g_wbTLO[o]);
    }
}
__global__ void k_W1TP(const float* __restrict__ W1){
    int i = blockIdx.x * 256 + threadIdx.x;
    int f = i >> 6, c = i & 63;
    split2(W1[c*FCD + f], g_W1THI[i], g_W1TLO[i]);
}
__global__ void k_WcP(const float* __restrict__ W_conv, int li){
    int i = blockIdx.x * 256 + threadIdx.x;
    split2(W_conv[(size_t)li*DIMC*DIMC + i], g_WcHI[i], g_WcLO[i]);
}
__global__ void k_buildH(const float* __restrict__ Do, const float* __restrict__ Di,
                         const float* __restrict__ pr, const float* __restrict__ A,
                         const float* __restrict__ Bm){
    int j = blockIdx.x, k = blockIdx.y, l = threadIdx.x;
    float s = Do[j*MODE + k] * Di[j*MODE + l] * pr[k*MODE + l];
    #pragma unroll
    for (int r = 0; r < RANKR; r++)
        s += A[(j*RANKR + r)*MODE + k] * Bm[(j*RANKR + r)*MODE + l];
    size_t o = ((size_t)j*MODE + k)*MODE + l;
    split2(s, g_HjHI[o], g_HjLO[o]);
}
__global__ void k_prep0(const float* __restrict__ W_conv, const float* __restrict__ W0,
                        const float* __restrict__ b0, const float* __restrict__ b_conv){
    int o = threadIdx.x;
    float w0s = 0.f, w1s = 0.f, w2s = 0.f, bb = b_conv[o];
    for (int c = 0; c < DIMC; c++){
        float wc = W_conv[o*DIMC + c];
        w0s += wc*W0[c]; w1s += wc*W0[DIMC+c]; w2s += wc*W0[2*DIMC+c];
        bb  += wc*b0[c];
    }
    g_Wc0T[o] = w0s; g_Wc0T[64+o] = w1s; g_Wc0T[128+o] = w2s; g_bias0[o] = bb;
}
__global__ void k_T(const float* __restrict__ wbases){
    int b = blockIdx.x, s = blockIdx.y;
    int x0 = s * (NXS / T_SPLITS);
    int k = threadIdx.x;
    __shared__ float xs[3][128];
    float a0=0.f, a1=0.f, a2=0.f, a3=0.f;
    for (int xt = 0; xt < (NXS/T_SPLITS)/128; xt++){
        __syncthreads();
        xs[0][k] = g_xT[((size_t)b*IN_DIM + 0)*NXS + x0 + xt*128 + k];
        xs[1][k] = g_xT[((size_t)b*IN_DIM + 1)*NXS + x0 + xt*128 + k];
        xs[2][k] = g_xT[((size_t)b*IN_DIM + 2)*NXS + x0 + xt*128 + k];
        __syncthreads();
        #pragma unroll 8
        for (int xi = 0; xi < 128; xi++){
            float w = wbases[(size_t)(x0 + xt*128 + xi)*MODE + k];
            a0 += xs[0][xi]*w; a1 += xs[1][xi]*w; a2 += xs[2][xi]*w; a3 += w;
        }
    }
    size_t base = (((size_t)s*BSZ + b)*4)*MODE + k;
    g_Tp[base] = a0; g_Tp[base+MODE] = a1; g_Tp[base+2*MODE] = a2; g_Tp[base+3*MODE] = a3;
}
__global__ void k_xh0(const float* __restrict__ W0, const float* __restrict__ b0){
    int b = blockIdx.x;
    __shared__ float Ts[4][128];
    int tid = threadIdx.x;
    for (int e = tid; e < 4*MODE; e += 256){
        int d = e >> 7, k = e & 127;
        float s = 0.f;
        #pragma unroll
        for (int s8 = 0; s8 < T_SPLITS; s8++)
            s += g_Tp[(((size_t)s8*BSZ + b)*4 + d)*MODE + k];
        Ts[d][k] = s;
    }
    __syncthreads();
    for (int o = tid; o < DIMC*MODE; o += 256){
        int c = o >> 7, k = o & 127;
        float v = W0[c]*Ts[0][k] + W0[DIMC+c]*Ts[1][k] + W0[2*DIMC+c]*Ts[2][k] + b0[c]*Ts[3][k];
        size_t idx = (size_t)b*DIMC*MODE + o;
        split2(v, g_xhHI[idx], g_xhLO[idx]);
    }
}

// ===== GEMM1 (single-sync pipeline) =====
__global__ void __launch_bounds__(256) k_xh_mma(const ushortx* __restrict__ hxHI,
                                                const ushortx* __restrict__ hxLO){
    __shared__ __align__(16) unsigned smA[2][2][16][68];
    __shared__ __align__(16) unsigned smB[2][2][128][12];
    const int NIT = (NXS/XH_SPLITS)/16;
    int tid = threadIdx.x, lane = tid & 31, wid = tid >> 5;
    int wm = wid >> 2, wn = wid & 3, g = lane >> 2, t = lane & 3;
    int m0 = blockIdx.x * 128, b0 = blockIdx.x * 2;
    int k0 = blockIdx.y * (NXS / XH_SPLITS);
    int xr = tid >> 4, bl = (tid >> 3) & 1, cq = tid & 7;
    const ushortx* sAh = hxHI + ((size_t)(b0+bl)*NXS + k0 + xr)*DIMC + cq*8;
    const ushortx* sAl = hxLO + ((size_t)(b0+bl)*NXS + k0 + xr)*DIMC + cq*8;
    unsigned dAh = (unsigned)__cvta_generic_to_shared(&smA[0][0][xr][bl*32 + cq*4]);
    unsigned dAl = (unsigned)__cvta_generic_to_shared(&smA[1][0][xr][bl*32 + cq*4]);
    int rB = tid >> 1, chB = tid & 1;
    const ushortx* sBh = g_wbTHI + (size_t)rB*NXS + k0 + chB*8;
    const ushortx* sBl = g_wbTLO + (size_t)rB*NXS + k0 + chB*8;
    unsigned dBh = (unsigned)__cvta_generic_to_shared(&smB[0][0][rB][chB*4]);
    unsigned dBl = (unsigned)__cvta_generic_to_shared(&smB[1][0][rB][chB*4]);
    unsigned bAh = (unsigned)__cvta_generic_to_shared(&smA[0][0][0][0]);
    unsigned bAl = (unsigned)__cvta_generic_to_shared(&smA[1][0][0][0]);
    unsigned bBh = (unsigned)__cvta_generic_to_shared(&smB[0][0][0][0]);
    unsigned bBl = (unsigned)__cvta_generic_to_shared(&smB[1][0][0][0]);
    const unsigned ABUFO = 16*68*4, BBUFO = 128*48;
    unsigned loffT = ((lane & 7) + (lane >> 4)*8)*272 + ((lane >> 3) & 1)*16;
    unsigned loff  = (lane & 15)*48 + (lane >> 4)*16;
    float c[4][4][4] = {};
    CPA(dAh, sAh); CPA(dAl, sAl); CPA(dBh, sBh); CPA(dBl, sBl);
    CPC();
    for (int it = 0; it < NIT; it++){
        int cur = it & 1, nxt = cur ^ 1;
        CPW0();
        __syncthreads();
        unsigned Ah[4][4], Al[4][4], Bh[2][4], Bl[2][4];
        #pragma unroll
        for (int tm = 0; tm < 4; tm++){
            LDSM4T(Ah[tm], bAh + cur*ABUFO + loffT + (wm*64 + tm*16)*2);
            LDSM4T(Al[tm], bAl + cur*ABUFO + loffT + (wm*64 + tm*16)*2);
        }
        #pragma unroll
        for (int p = 0; p < 2; p++){
            LDSM4(Bh[p], bBh + cur*BBUFO + loff + (wn*32 + p*16)*48);
            LDSM4(Bl[p], bBl + cur*BBUFO + loff + (wn*32 + p*16)*48);
        }
        if (it + 1 < NIT){
            CPA(dAh + nxt*ABUFO, sAh + (size_t)(it+1)*16*DIMC);
            CPA(dAl + nxt*ABUFO, sAl + (size_t)(it+1)*16*DIMC);
            CPA(dBh + nxt*BBUFO, sBh + (it+1)*16);
            CPA(dBl + nxt*BBUFO, sBl + (it+1)*16);
            CPC();
        }
        #pragma unroll
        for (int tm = 0; tm < 4; tm++)
            #pragma unroll
            for (int tn = 0; tn < 4; tn++){
                int p = tn >> 1, e = tn & 1;
                unsigned bh[2] = {Bh[p][e], Bh[p][e+2]};
                unsigned bl[2] = {Bl[p][e], Bl[p][e+2]};
                MMA(c[tm][tn], Ah[tm], bh);
                MMA(c[tm][tn], Al[tm], bh);
                MMA(c[tm][tn], Ah[tm], bl);
            }
    }
    float* dst = &g_xhp[(size_t)blockIdx.y*(BSZ*DIMC*MODE)];
    #pragma unroll
    for (int tm = 0; tm < 4; tm++)
        #pragma unroll
        for (int tn = 0; tn < 4; tn++){
            int m = m0 + wm*64 + tm*16 + g;
            int n = wn*32 + tn*8 + t*2;
            *(float2*)&dst[(size_t)m*MODE + n]     = make_float2(c[tm][tn][0], c[tm][tn][1]);
            *(float2*)&dst[(size_t)(m+8)*MODE + n] = make_float2(c[tm][tn][2], c[tm][tn][3]);
        }
}
__global__ void k_reduce_xh(){
    int i = blockIdx.x * 256 + threadIdx.x;
    float s = 0.f;
    #pragma unroll
    for (int k = 0; k < XH_SPLITS; k++) s += g_xhp[(size_t)k*(BSZ*DIMC*MODE) + i];
    split2(s, g_xhHI[i], g_xhLO[i]);
}

// ===== xh1 (mma, single-sync) =====
__global__ void __launch_bounds__(256) k_xh1_mma(){
    __shared__ __align__(16) unsigned smA[2][2][64][12];
    __shared__ __align__(16) unsigned smB[2][2][128][12];
    int tid = threadIdx.x, lane = tid & 31, wid = tid >> 5;
    int wm = wid >> 2, wn = wid & 3, g = lane >> 2, t = lane & 3;
    int b = blockIdx.x, j = blockIdx.y;
    unsigned loff = (lane & 15)*48 + (lane >> 4)*16;
    int aA = tid >> 7, rA = (tid >> 1) & 63, hA = tid & 1;
    const ushortx* srcA = (aA ? g_xhLO : g_xhHI) + ((size_t)b*DIMC + rA)*MODE + hA*8;
    unsigned dA = (unsigned)__cvta_generic_to_shared(&smA[aA][0][rA][hA*4]);
    unsigned bAh = (unsigned)__cvta_generic_to_shared(&smA[0][0][0][0]);
    unsigned bAl = (unsigned)__cvta_generic_to_shared(&smA[1][0][0][0]);
    unsigned bBh = (unsigned)__cvta_generic_to_shared(&smB[0][0][0][0]);
    unsigned bBl = (unsigned)__cvta_generic_to_shared(&smB[1][0][0][0]);
    const unsigned ABUFO = 64*12*4, BBUFO = 128*12*4;
    float c[2][4][4] = {};
    CPA(dA, srcA);
    #pragma unroll
    for (int rep = 0; rep < 2; rep++){
        int cid = tid + rep*256;
        int aB = cid >> 8, rBx = (cid >> 1) & 127, hB = cid & 1;
        const ushortx* srcB = (aB ? g_HjLO : g_HjHI) + ((size_t)j*MODE + rBx)*MODE + hB*8;
        CPA((unsigned)__cvta_generic_to_shared(&smB[aB][0][rBx][hB*4]), srcB);
    }
    CPC();
    for (int ks = 0; ks < 8; ks++){
        int cur = ks & 1, nxt = cur ^ 1;
        CPW0();
        __syncthreads();
        unsigned offA = cur*ABUFO + loff, offB = cur*BBUFO + loff;
        unsigned Ah[2][4], Al[2][4], Bh[2][4], Bl[2][4];
        #pragma unroll
        for (int tm = 0; tm < 2; tm++){
            LDSM4(Ah[tm], bAh + offA + (wm*32 + tm*16)*48);
            LDSM4(Al[tm], bAl + offA + (wm*32 + tm*16)*48);
        }
        #pragma unroll
        for (int p = 0; p < 2; p++){
            LDSM4(Bh[p], bBh + offB + (wn*32 + p*16)*48);
            LDSM4(Bl[p], bBl + offB + (wn*32 + p*16)*48);
        }
        if (ks + 1 < 8){
            CPA(dA + nxt*ABUFO, srcA + (ks+1)*16);
            #pragma unroll
            for (int rep = 0; rep < 2; rep++){
                int cid = tid + rep*256;
                int aB = cid >> 8, rBx = (cid >> 1) & 127, hB = cid & 1;
                const ushortx* srcB = (aB ? g_HjLO : g_HjHI) + ((size_t)j*MODE + rBx)*MODE + hB*8;
                CPA((unsigned)__cvta_generic_to_shared(&smB[aB][0][rBx][hB*4]) + nxt*BBUFO,
                    srcB + (ks+1)*16);
            }
            CPC();
        }
        #pragma unroll
        for (int tm = 0; tm < 2; tm++)
            #pragma unroll
            for (int tn = 0; tn < 4; tn++){
                int p = tn >> 1, e = tn & 1;
                unsigned bh[2] = {Bh[p][e], Bh[p][e+2]};
                unsigned bl[2] = {Bl[p][e], Bl[p][e+2]};
                MMA(c[tm][tn], Ah[tm], bh);
                MMA(c[tm][tn], Al[tm], bh);
                MMA(c[tm][tn], Ah[tm], bl);
            }
    }
    #pragma unroll
    for (int tm = 0; tm < 2; tm++)
        #pragma unroll
        for (int tn = 0; tn < 4; tn++){
            int m = wm*32 + tm*16 + g;
            int n = wn*32 + tn*8 + t*2;
            #pragma unroll
            for (int e = 0; e < 4; e++){
                int mm = m + (e >> 1)*8, nn = n + (e & 1);
                size_t o = ((size_t)b*MODE + nn)*(DIMC*NJ) + j*64 + mm;
                split2(c[tm][tn][e], g_x1THI[o], g_x1TLO[o]);
            }
        }
}
__global__ void k_WrT(const float* __restrict__ W_sp, int li){
    int idx = blockIdx.x * 256 + threadIdx.x;
    int p = idx & 1023, o = idx >> 10;
    int j = p >> 6, cc = p & 63;
    float v = W_sp[(((size_t)li*DIMC + cc)*DIMC + o)*NJ + j];
    split2(v, g_WrTTHI[idx], g_WrTTLO[idx]);
}
__global__ void __launch_bounds__(256) k_y_mma(){
    __shared__ __align__(16) unsigned smA[2][2][64][12];
    __shared__ __align__(16) unsigned smB[2][2][128][12];
    int tid = threadIdx.x, lane = tid & 31, wid = tid >> 5;
    int wm = wid >> 2, wn = wid & 3, g = lane >> 2, t = lane & 3;
    int b = blockIdx.x, sp = blockIdx.y;
    int p0 = sp * 256;
    unsigned loff = (lane & 15)*48 + (lane >> 4)*16;
    int aA = tid >> 7, rA = (tid >> 1) & 63, hA = tid & 1;
    const ushortx* srcA = (aA ? g_WrTTLO : g_WrTTHI) + (size_t)rA*(DIMC*NJ) + p0 + hA*8;
    unsigned dA = (unsigned)__cvta_generic_to_shared(&smA[aA][0][rA][hA*4]);
    unsigned bAh = (unsigned)__cvta_generic_to_shared(&smA[0][0][0][0]);
    unsigned bAl = (unsigned)__cvta_generic_to_shared(&smA[1][0][0][0]);
    unsigned bBh = (unsigned)__cvta_generic_to_shared(&smB[0][0][0][0]);
    unsigned bBl = (unsigned)__cvta_generic_to_shared(&smB[1][0][0][0]);
    const unsigned ABUFO = 64*12*4, BBUFO = 128*12*4;
    float c[2][4][4] = {};
    CPA(dA, srcA);
    #pragma unroll
    for (int rep = 0; rep < 2; rep++){
        int cid = tid + rep*256;
        int aB = cid >> 8, rBx = (cid >> 1) & 127, hB = cid & 1;
        const ushortx* srcB = (aB ? g_x1TLO : g_x1THI) + ((size_t)b*MODE + rBx)*(DIMC*NJ) + p0 + hB*8;
        CPA((unsigned)__cvta_generic_to_shared(&smB[aB][0][rBx][hB*4]), srcB);
    }
    CPC();
    for (int ks = 0; ks < 16; ks++){
        int cur = ks & 1, nxt = cur ^ 1;
        CPW0();
        __syncthreads();
        unsigned offA = cur*ABUFO + loff, offB = cur*BBUFO + loff;
        unsigned Ah[2][4], Al[2][4], Bh[2][4], Bl[2][4];
        #pragma unroll
        for (int tm = 0; tm < 2; tm++){
            LDSM4(Ah[tm], bAh + offA + (wm*32 + tm*16)*48);
            LDSM4(Al[tm], bAl + offA + (wm*32 + tm*16)*48);
        }
        #pragma unroll
        for (int p = 0; p < 2; p++){
            LDSM4(Bh[p], bBh + offB + (wn*32 + p*16)*48);
            LDSM4(Bl[p], bBl + offB + (wn*32 + p*16)*48);
        }
        if (ks + 1 < 16){
            CPA(dA + nxt*ABUFO, srcA + (ks+1)*16);
            #pragma unroll
            for (int rep = 0; rep < 2; rep++){
                int cid = tid + rep*256;
                int aB = cid >> 8, rBx = (cid >> 1) & 127, hB = cid & 1;
                const ushortx* srcB = (aB ? g_x1TLO : g_x1THI) + ((size_t)b*MODE + rBx)*(DIMC*NJ) + p0 + hB*8;
                CPA((unsigned)__cvta_generic_to_shared(&smB[aB][0][rBx][hB*4]) + nxt*BBUFO,
                    srcB + (ks+1)*16);
            }
            CPC();
        }
        #pragma unroll
        for (int tm = 0; tm < 2; tm++)
            #pragma unroll
            for (int tn = 0; tn < 4; tn++){
                int p = tn >> 1, e = tn & 1;
                unsigned bh[2] = {Bh[p][e], Bh[p][e+2]};
                unsigned bl[2] = {Bl[p][e], Bl[p][e+2]};
                MMA(c[tm][tn], Ah[tm], bh);
                MMA(c[tm][tn], Al[tm], bh);
                MMA(c[tm][tn], Ah[tm], bl);
            }
    }
    float* dst = &g_yp[(size_t)sp*(BSZ*DIMC*MODE)];
    #pragma unroll
    for (int tm = 0; tm < 2; tm++)
        #pragma unroll
        for (int tn = 0; tn < 4; tn++){
            int m = wm*32 + tm*16 + g;
            int n = wn*32 + tn*8 + t*2;
            *(float2*)&dst[((size_t)b*DIMC + m)*MODE + n]     = make_float2(c[tm][tn][0], c[tm][tn][1]);
            *(float2*)&dst[((size_t)b*DIMC + m + 8)*MODE + n] = make_float2(c[tm][tn][2], c[tm][tn][3]);
        }
}
__global__ void k_reduce_y(){
    int i = blockIdx.x * 256 + threadIdx.x;
    float s = 0.f;
    #pragma unroll
    for (int k = 0; k < Y_SPLITS; k++) s += g_yp[(size_t)k*(BSZ*DIMC*MODE) + i];
    split2(s, g_yHI[i], g_yLO[i]);
}

// ===== GEMM2 + tensorized fc1 (single-sync pipeline; grid swapped for bases reuse) =====
#define CSW 132
#define AHI_OFF 0
#define ALO_OFF 12288
#define BHI_OFF 24576
#define BLO_OFF 30720
#define ABUF 6144
#define BBUF 3072
#define FAHI 36864
#define FALO 43008
#define FBHI 49152
#define FBLO 55296
#define LSM_LAST 61440
#define LSM_MID  36864
__global__ void __launch_bounds__(256) k_L_mma(
    const ushortx* __restrict__ hxHI, const ushortx* __restrict__ hxLO,
    ushortx* __restrict__ hxoHI, ushortx* __restrict__ hxoLO,
    const float* __restrict__ biasv,
    const float* __restrict__ b1, const float* __restrict__ W2,
    const float* __restrict__ b2,
    float* __restrict__ out, int tail3, int is_last)
{
    extern __shared__ __align__(16) char pool[];
    float (*Csm)[CSW]  = (float(*)[CSW])pool;
    unsigned (*CsmU)[CSW] = (unsigned(*)[CSW])pool;
    int tid = threadIdx.x, lane = tid & 31, wid = tid >> 5;
    int wm = wid >> 2, wn = wid & 3, g = lane >> 2, t = lane & 3;
    int b = blockIdx.x;                 // swapped: co-scheduled blocks share x0
    int x0 = blockIdx.y * 128;
    int row = tid >> 1, ch = tid & 1;
    int nch = tail3 ? 8 : 12;
    unsigned sbase = (unsigned)__cvta_generic_to_shared(pool);
    unsigned dAhi = sbase + AHI_OFF + row*48 + ch*16;
    unsigned dAlo = dAhi + (ALO_OFF - AHI_OFF);
    unsigned bAhi = sbase + AHI_OFF, bAlo = sbase + ALO_OFF;
    unsigned bBhi = sbase + BHI_OFF, bBlo = sbase + BLO_OFF;
    int bhalf = tid >> 7, bo = (tid >> 1) & 63, bh = tid & 1;
    const ushortx* sBy = (bhalf ? g_yLO : g_yHI) + ((size_t)b*DIMC + bo)*MODE + bh*8;
    const ushortx* sBw = (bhalf ? g_WcLO : g_WcHI) + (size_t)bo*DIMC + bh*8;
    unsigned dB = sbase + (bhalf ? BLO_OFF : BHI_OFF) + bo*48 + bh*16;
    unsigned loff = (lane & 15)*48 + (lane >> 4)*16;
    float c[4][2][4] = {};
    CPA(dAhi, g_basesHI + (size_t)(x0+row)*MODE + ch*8);
    CPA(dAlo, g_basesLO + (size_t)(x0+row)*MODE + ch*8);
    CPA(dB, sBy);
    CPC();
    for (int chn = 0; chn < nch; chn++){
        int cur = chn & 1, nxt = cur ^ 1;
        CPW0();
        __syncthreads();
        unsigned offA = cur*ABUF + loff;
        unsigned offB = cur*BBUF + loff;
        unsigned Ah[4][4], Al[4][4], Bh[4], Bl[4];
        #pragma unroll
        for (int tm = 0; tm < 4; tm++){
            LDSM4(Ah[tm], bAhi + offA + (wm*64 + tm*16)*48);
            LDSM4(Al[tm], bAlo + offA + (wm*64 + tm*16)*48);
        }
        LDSM4(Bh, bBhi + offB + (wn*16)*48);
        LDSM4(Bl, bBlo + offB + (wn*16)*48);
        if (chn + 1 < nch){
            int cn = chn + 1;
            if (cn < 8){
                CPA(dAhi + nxt*ABUF, g_basesHI + (size_t)(x0+row)*MODE + cn*16 + ch*8);
                CPA(dAlo + nxt*ABUF, g_basesLO + (size_t)(x0+row)*MODE + cn*16 + ch*8);
                CPA(dB + nxt*BBUF, sBy + cn*16);
            } else {
                CPA(dAhi + nxt*ABUF, hxHI + ((size_t)b*NXS + x0 + row)*DIMC + (cn-8)*16 + ch*8);
                CPA(dAlo + nxt*ABUF, hxLO + ((size_t)b*NXS + x0 + row)*DIMC + (cn-8)*16 + ch*8);
                CPA(dB + nxt*BBUF, sBw + (cn-8)*16);
            }
            CPC();
        }
        #pragma unroll
        for (int tm = 0; tm < 4; tm++)
            #pragma unroll
            for (int tn = 0; tn < 2; tn++){
                unsigned bhv[2] = {Bh[tn], Bh[tn+2]};
                unsigned blv[2] = {Bl[tn], Bl[tn+2]};
                MMA(c[tm][tn], Ah[tm], bhv);
                MMA(c[tm][tn], Al[tm], bhv);
                MMA(c[tm][tn], Ah[tm], blv);
            }
    }
    __syncthreads();
    #pragma unroll
    for (int tm = 0; tm < 4; tm++)
        #pragma unroll
        for (int tn = 0; tn < 2; tn++){
            int xr = wm*64 + tm*16 + g;
            int oc = wn*16 + tn*8 + t*2;
            Csm[oc][xr]     = c[tm][tn][0]; Csm[oc+1][xr]   = c[tm][tn][1];
            Csm[oc][xr+8]   = c[tm][tn][2]; Csm[oc+1][xr+8] = c[tm][tn][3];
        }
    __syncthreads();
    {
        int o = tid >> 2;
        float bias = tail3 ? g_bias0[o] : biasv[o];
        float w0 = 0.f, w1 = 0.f, w2c = 0.f;
        if (tail3){ w0 = g_Wc0T[o]; w1 = g_Wc0T[64+o]; w2c = g_Wc0T[128+o]; }
        #pragma unroll 4
        for (int j = 0; j < 32; j++){
            int xr = (tid & 3)*32 + j;
            float v = Csm[o][xr] + bias;
            if (tail3){
                int gx = x0 + xr;
                v += g_xT[((size_t)b*IN_DIM + 0)*NXS + gx]*w0
                   + g_xT[((size_t)b*IN_DIM + 1)*NXS + gx]*w1
                   + g_xT[((size_t)b*IN_DIM + 2)*NXS + gx]*w2c;
            }
            if (!is_last) CsmU[o][xr] = pk_split(gelu_f(v));
            else          Csm[o][xr] = v;
        }
    }
    __syncthreads();
    if (!is_last){
        for (int i = tid; i < 128*32; i += 256){
            int xx = i >> 5, cp = i & 31;
            unsigned u0 = CsmU[2*cp][xx], u1 = CsmU[2*cp+1][xx];
            unsigned hi = (u0 >> 16) | (u1 & 0xFFFF0000u);
            unsigned lo = (u0 & 0xFFFFu) | (u1 << 16);
            size_t base = ((size_t)b*NXS + x0 + xx)*DIMC;
            ((unsigned*)(hxoHI + base))[cp] = hi;
            ((unsigned*)(hxoLO + base))[cp] = lo;
        }
        return;
    }
    float c2[4][4][4] = {};
    int hh_ = tid & 1, xr_ = tid >> 1;
    for (int ks = 0; ks < 4; ks++){
        CPA(sbase + FBHI + row*48 + hh_*16, g_W1THI + row*64 + ks*16 + hh_*8);
        CPA(sbase + FBLO + row*48 + hh_*16, g_W1TLO + row*64 + ks*16 + hh_*8);
        CPC();
        {
            unsigned uh[4], ul[4];
            #pragma unroll
            for (int j = 0; j < 4; j++){
                ushortx h0,l0,h1,l1;
                split2(Csm[ks*16 + hh_*8 + 2*j][xr_], h0, l0);
                split2(Csm[ks*16 + hh_*8 + 2*j+1][xr_], h1, l1);
                uh[j] = (unsigned)h0 | ((unsigned)h1 << 16);
                ul[j] = (unsigned)l0 | ((unsigned)l1 << 16);
            }
            *(uint4*)(pool + FAHI + xr_*48 + hh_*16) = make_uint4(uh[0],uh[1],uh[2],uh[3]);
            *(uint4*)(pool + FALO + xr_*48 + hh_*16) = make_uint4(ul[0],ul[1],ul[2],ul[3]);
        }
        CPW0();
        __syncthreads();
        unsigned Ah[4][4], Al[4][4], Bh[2][4], Bl[2][4];
        #pragma unroll
        for (int tm = 0; tm < 4; tm++){
            LDSM4(Ah[tm], sbase + FAHI + loff + (wm*64 + tm*16)*48);
            LDSM4(Al[tm], sbase + FALO + loff + (wm*64 + tm*16)*48);
        }
        #pragma unroll
        for (int p = 0; p < 2; p++){
            LDSM4(Bh[p], sbase + FBHI + loff + (wn*32 + p*16)*48);
            LDSM4(Bl[p], sbase + FBLO + loff + (wn*32 + p*16)*48);
        }
        #pragma unroll
        for (int tm = 0; tm < 4; tm++)
            #pragma unroll
            for (int tn = 0; tn < 4; tn++){
                int p = tn >> 1, e = tn & 1;
                unsigned bh[2] = {Bh[p][e], Bh[p][e+2]};
                unsigned bl[2] = {Bl[p][e], Bl[p][e+2]};
                MMA(c2[tm][tn], Ah[tm], bh);
                MMA(c2[tm][tn], Al[tm], bh);
                MMA(c2[tm][tn], Ah[tm], bl);
            }
        __syncthreads();
    }
    float part[4][2] = {};
    #pragma unroll
    for (int tn = 0; tn < 4; tn++){
        int f0 = wn*32 + tn*8 + t*2;
        float b10 = b1[f0], b11 = b1[f0+1];
        float w20 = W2[f0], w21 = W2[f0+1];
        #pragma unroll
        for (int tm = 0; tm < 4; tm++){
            part[tm][0] += gelu_f(c2[tm][tn][0]+b10)*w20 + gelu_f(c2[tm][tn][1]+b11)*w21;
            part[tm][1] += gelu_f(c2[tm][tn][2]+b10)*w20 + gelu_f(c2[tm][tn][3]+b11)*w21;
        }
    }
    float (*red)[16] = (float(*)[16])(pool + FAHI);
    #pragma unroll
    for (int tm = 0; tm < 4; tm++){
        int xr0 = wm*64 + tm*16 + g;
        red[xr0][wn*4 + t]   = part[tm][0];
        red[xr0+8][wn*4 + t] = part[tm][1];
    }
    __syncthreads();
    if (tid < 128){
        float s = b2[0];
        #pragma unroll
        for (int k = 0; k < 16; k++) s += red[tid][k];
        out[(size_t)b*NXS + x0 + tid] = s;
    }
}

// ---------------------------------------------------------------------------
extern "C" void kernel_launch(void* const* d_in, const int* in_sizes, int n_in,
                              void* d_out, int out_size){
    (void)in_sizes; (void)n_in; (void)out_size;
    const float* x      = (const float*)d_in[0];
    const float* bases  = (const float*)d_in[1];
    const float* wbases = (const float*)d_in[2];
    const float* product= (const float*)d_in[3];
    const float* Do     = (const float*)d_in[4];
    const float* Di     = (const float*)d_in[5];
    const float* A      = (const float*)d_in[6];
    const float* Bm     = (const float*)d_in[7];
    const float* W_sp   = (const float*)d_in[8];
    const float* W_conv = (const float*)d_in[9];
    const float* b_conv = (const float*)d_in[10];
    const float* W0     = (const float*)d_in[11];
    const float* b0     = (const float*)d_in[12];
    const float* W1     = (const float*)d_in[13];
    const float* b1     = (const float*)d_in[14];
    const float* W2     = (const float*)d_in[15];
    const float* b2     = (const float*)d_in[16];
    float* out = (float*)d_out;

    cudaFuncSetAttribute(k_L_mma, cudaFuncAttributeMaxDynamicSharedMemorySize, LSM_LAST);

    ushortx *hxHa,*hxLa,*hxHb,*hxLb;
    cudaGetSymbolAddress((void**)&hxHa, g_hxHIa);
    cudaGetSymbolAddress((void**)&hxLa, g_hxLOa);
    cudaGetSymbolAddress((void**)&hxHb, g_hxHIb);
    cudaGetSymbolAddress((void**)&hxLb, g_hxLOb);

    k_basesP<<<(NXS*MODE)/256, 256>>>(bases);
    k_wbTP<<<dim3(NXS/32, MODE/32), dim3(32,8)>>>(wbases);
    k_W1TP<<<(FCD*DIMC)/256, 256>>>(W1);
    k_buildH<<<dim3(NJ, MODE), MODE>>>(Do, Di, product, A, Bm);
    k_xT<<<(BSZ*NXS*IN_DIM)/256, 256>>>(x);
    k_prep0<<<1, DIMC>>>(W_conv, W0, b0, b_conv);

    // ---- layer 0 ----
    k_T<<<dim3(BSZ, T_SPLITS), MODE>>>(wbases);
    k_xh0<<<BSZ, 256>>>(W0, b0);
    k_xh1_mma<<<dim3(BSZ, NJ), 256>>>();
    k_WrT<<<(DIMC*DIMC*NJ)/256, 256>>>(W_sp, 0);
    k_y_mma<<<dim3(BSZ, Y_SPLITS), 256>>>();
    k_reduce_y<<<(BSZ*DIMC*MODE)/256, 256>>>();
    k_L_mma<<<dim3(BSZ, NXS/128), 256, LSM_MID>>>(hxHa, hxLa, hxHa, hxLa,
                                                  nullptr,
                                                  b1, W2, b2, out, 1, 0);
    // ---- layers 1,2 ----
    const ushortx *hxH = hxHa, *hxL = hxLa;
    ushortx *hxHo = hxHb, *hxLo = hxLb;
    for (int li = 1; li < N_LAYERS; li++){
        int last = (li == N_LAYERS-1) ? 1 : 0;
        k_xh_mma<<<dim3((BSZ*DIMC)/128, XH_SPLITS), 256>>>(hxH, hxL);
        k_reduce_xh<<<(BSZ*DIMC*MODE)/256, 256>>>();
        k_xh1_mma<<<dim3(BSZ, NJ), 256>>>();
        k_WrT<<<(DIMC*DIMC*NJ)/256, 256>>>(W_sp, li);
        k_y_mma<<<dim3(BSZ, Y_SPLITS), 256>>>();
        k_reduce_y<<<(BSZ*DIMC*MODE)/256, 256>>>();
        k_WcP<<<(DIMC*DIMC)/256, 256>>>(W_conv, li);
        k_L_mma<<<dim3(BSZ, NXS/128), 256, last ? LSM_LAST : LSM_MID>>>(
                                             hxH, hxL, hxHo, hxLo,
                                             &b_conv[(size_t)li*DIMC],
                                             b1, W2, b2, out, 0, last);
        const ushortx* t3 = hxH; hxH = hxHo; hxHo = (ushortx*)t3;
        const ushortx* t4 = hxL; hxL = hxLo; hxLo = (ushortx*)t4;
    }
}

// round 14
// speedup vs baseline: 1.0808x; 1.0808x over previous
#include <cuda_runtime.h>
#include <cuda_bf16.h>
#include <math.h>
#include <stdint.h>

#define BSZ 32
#define NXS 16384
#define IN_DIM 3
#define DIMC 64
#define NJ 16
#define MODE 128
#define RANKR 4
#define FCD 128
#define N_LAYERS 3
#define XH_SPLITS 8
#define Y_SPLITS 4
#define T_SPLITS 8

typedef unsigned short ushortx;

__device__ ushortx g_hxHIa[(size_t)BSZ*NXS*DIMC];
__device__ ushortx g_hxLOa[(size_t)BSZ*NXS*DIMC];
__device__ ushortx g_hxHIb[(size_t)BSZ*NXS*DIMC];
__device__ ushortx g_hxLOb[(size_t)BSZ*NXS*DIMC];
__device__ ushortx g_wbTHI[(size_t)MODE*NXS];
__device__ ushortx g_wbTLO[(size_t)MODE*NXS];
__device__ ushortx g_basesHI[(size_t)NXS*MODE];
__device__ ushortx g_basesLO[(size_t)NXS*MODE];
__device__ ushortx g_W1THI[FCD*DIMC];
__device__ ushortx g_W1TLO[FCD*DIMC];
__device__ ushortx g_HjHI[NJ*MODE*MODE];
__device__ ushortx g_HjLO[NJ*MODE*MODE];
__device__ ushortx g_xhHI[BSZ*DIMC*MODE];
__device__ ushortx g_xhLO[BSZ*DIMC*MODE];
__device__ ushortx g_x1THI[(size_t)BSZ*MODE*(DIMC*NJ)];
__device__ ushortx g_x1TLO[(size_t)BSZ*MODE*(DIMC*NJ)];
__device__ ushortx g_WrTTHI[DIMC*DIMC*NJ];
__device__ ushortx g_WrTTLO[DIMC*DIMC*NJ];
__device__ ushortx g_yHI[BSZ*DIMC*MODE];
__device__ ushortx g_yLO[BSZ*DIMC*MODE];
__device__ ushortx g_WcHI[DIMC*DIMC];
__device__ ushortx g_WcLO[DIMC*DIMC];
__device__ float g_xT[BSZ*IN_DIM*NXS];
__device__ float g_xhp[XH_SPLITS*BSZ*DIMC*MODE];
__device__ float g_yp [Y_SPLITS*BSZ*DIMC*MODE];
__device__ float g_Tp [T_SPLITS*BSZ*4*MODE];
__device__ float g_Wc0T[IN_DIM*DIMC];
__device__ float g_bias0[DIMC];

__device__ __forceinline__ float gelu_f(float v){
    return 0.5f * v * (1.0f + erff(v * 0.70710678118654752440f));
}
__device__ __forceinline__ void split2(float x, ushortx& hi, ushortx& lo){
    __nv_bfloat16 h = __float2bfloat16(x);
    hi = __bfloat16_as_ushort(h);
    lo = __bfloat16_as_ushort(__float2bfloat16(x - __bfloat162float(h)));
}
__device__ __forceinline__ unsigned pk_split(float x){
    ushortx hi, lo; split2(x, hi, lo);
    return ((unsigned)hi << 16) | (unsigned)lo;
}
#define MMA(c,a,b) asm volatile( \
    "mma.sync.aligned.m16n8k16.row.col.f32.bf16.bf16.f32 " \
    "{%0,%1,%2,%3}, {%4,%5,%6,%7}, {%8,%9}, {%0,%1,%2,%3};" \
    : "+f"((c)[0]), "+f"((c)[1]), "+f"((c)[2]), "+f"((c)[3]) \
    : "r"((a)[0]), "r"((a)[1]), "r"((a)[2]), "r"((a)[3]), "r"((b)[0]), "r"((b)[1]))
#define LDSM4(f,addr) asm volatile( \
    "ldmatrix.sync.aligned.m8n8.x4.shared.b16 {%0,%1,%2,%3}, [%4];" \
    : "=r"((f)[0]), "=r"((f)[1]), "=r"((f)[2]), "=r"((f)[3]) : "r"(addr))
#define LDSM4T(f,addr) asm volatile( \
    "ldmatrix.sync.aligned.m8n8.x4.trans.shared.b16 {%0,%1,%2,%3}, [%4];" \
    : "=r"((f)[0]), "=r"((f)[1]), "=r"((f)[2]), "=r"((f)[3]) : "r"(addr))
#define CPA(dst,src) asm volatile("cp.async.cg.shared.global [%0], [%1], 16;" :: "r"(dst), "l"(src))
#define CPC() asm volatile("cp.async.commit_group;" ::: "memory")
#define CPW1() asm volatile("cp.async.wait_group 1;" ::: "memory")
#define CPW0() asm volatile("cp.async.wait_group 0;" ::: "memory")

// ---------------- prep ----------------
__global__ void k_xT(const float* __restrict__ x){
    int i = blockIdx.x * 256 + threadIdx.x;
    int d = i % 3, t = i / 3;
    g_xT[((size_t)(t >> 14)*IN_DIM + d)*NXS + (t & (NXS-1))] = x[i];
}
__global__ void k_basesP(const float* __restrict__ bases){
    int i = blockIdx.x * 256 + threadIdx.x;
    split2(bases[i], g_basesHI[i], g_basesLO[i]);
}
__global__ void k_wbTP(const float* __restrict__ wb){
    __shared__ float t[32][33];
    int x0 = blockIdx.x * 32, k0 = blockIdx.y * 32;
    for (int i = threadIdx.y; i < 32; i += 8)
        t[i][threadIdx.x] = wb[(size_t)(x0 + i)*MODE + k0 + threadIdx.x];
    __syncthreads();
    for (int i = threadIdx.y; i < 32; i += 8){
        size_t o = (size_t)(k0 + i)*NXS + x0 + threadIdx.x;
        split2(t[threadIdx.x][i], g_wbTHI[o], g_wbTLO[o]);
    }
}
__global__ void k_W1TP(const float* __restrict__ W1){
    int i = blockIdx.x * 256 + threadIdx.x;
    int f = i >> 6, c = i & 63;
    split2(W1[c*FCD + f], g_W1THI[i], g_W1TLO[i]);
}
__global__ void k_WcP(const float* __restrict__ W_conv, int li){
    int i = blockIdx.x * 256 + threadIdx.x;
    split2(W_conv[(size_t)li*DIMC*DIMC + i], g_WcHI[i], g_WcLO[i]);
}
__global__ void k_buildH(const float* __restrict__ Do, const float* __restrict__ Di,
                         const float* __restrict__ pr, const float* __restrict__ A,
                         const float* __restrict__ Bm){
    int j = blockIdx.x, k = blockIdx.y, l = threadIdx.x;
    float s = Do[j*MODE + k] * Di[j*MODE + l] * pr[k*MODE + l];
    #pragma unroll
    for (int r = 0; r < RANKR; r++)
        s += A[(j*RANKR + r)*MODE + k] * Bm[(j*RANKR + r)*MODE + l];
    size_t o = ((size_t)j*MODE + k)*MODE + l;
    split2(s, g_HjHI[o], g_HjLO[o]);
}
__global__ void k_prep0(const float* __restrict__ W_conv, const float* __restrict__ W0,
                        const float* __restrict__ b0, const float* __restrict__ b_conv){
    int o = threadIdx.x;
    float w0s = 0.f, w1s = 0.f, w2s = 0.f, bb = b_conv[o];
    for (int c = 0; c < DIMC; c++){
        float wc = W_conv[o*DIMC + c];
        w0s += wc*W0[c]; w1s += wc*W0[DIMC+c]; w2s += wc*W0[2*DIMC+c];
        bb  += wc*b0[c];
    }
    g_Wc0T[o] = w0s; g_Wc0T[64+o] = w1s; g_Wc0T[128+o] = w2s; g_bias0[o] = bb;
}
__global__ void k_T(const float* __restrict__ wbases){
    int b = blockIdx.x, s = blockIdx.y;
    int x0 = s * (NXS / T_SPLITS);
    int k = threadIdx.x;
    __shared__ float xs[3][128];
    float a0=0.f, a1=0.f, a2=0.f, a3=0.f;
    for (int xt = 0; xt < (NXS/T_SPLITS)/128; xt++){
        __syncthreads();
        xs[0][k] = g_xT[((size_t)b*IN_DIM + 0)*NXS + x0 + xt*128 + k];
        xs[1][k] = g_xT[((size_t)b*IN_DIM + 1)*NXS + x0 + xt*128 + k];
        xs[2][k] = g_xT[((size_t)b*IN_DIM + 2)*NXS + x0 + xt*128 + k];
        __syncthreads();
        #pragma unroll 8
        for (int xi = 0; xi < 128; xi++){
            float w = wbases[(size_t)(x0 + xt*128 + xi)*MODE + k];
            a0 += xs[0][xi]*w; a1 += xs[1][xi]*w; a2 += xs[2][xi]*w; a3 += w;
        }
    }
    size_t base = (((size_t)s*BSZ + b)*4)*MODE + k;
    g_Tp[base] = a0; g_Tp[base+MODE] = a1; g_Tp[base+2*MODE] = a2; g_Tp[base+3*MODE] = a3;
}
__global__ void k_xh0(const float* __restrict__ W0, const float* __restrict__ b0){
    int b = blockIdx.x;
    __shared__ float Ts[4][128];
    int tid = threadIdx.x;
    for (int e = tid; e < 4*MODE; e += 256){
        int d = e >> 7, k = e & 127;
        float s = 0.f;
        #pragma unroll
        for (int s8 = 0; s8 < T_SPLITS; s8++)
            s += g_Tp[(((size_t)s8*BSZ + b)*4 + d)*MODE + k];
        Ts[d][k] = s;
    }
    __syncthreads();
    for (int o = tid; o < DIMC*MODE; o += 256){
        int c = o >> 7, k = o & 127;
        float v = W0[c]*Ts[0][k] + W0[DIMC+c]*Ts[1][k] + W0[2*DIMC+c]*Ts[2][k] + b0[c]*Ts[3][k];
        size_t idx = (size_t)b*DIMC*MODE + o;
        split2(v, g_xhHI[idx], g_xhLO[idx]);
    }
}

// ===== GEMM1 (R12 pipeline: CPW1) =====
__global__ void __launch_bounds__(256) k_xh_mma(const ushortx* __restrict__ hxHI,
                                                const ushortx* __restrict__ hxLO){
    __shared__ __align__(16) unsigned smA[2][2][16][68];
    __shared__ __align__(16) unsigned smB[2][2][128][12];
    const int NIT = (NXS/XH_SPLITS)/16;
    int tid = threadIdx.x, lane = tid & 31, wid = tid >> 5;
    int wm = wid >> 2, wn = wid & 3, g = lane >> 2, t = lane & 3;
    int m0 = blockIdx.x * 128, b0 = blockIdx.x * 2;
    int k0 = blockIdx.y * (NXS / XH_SPLITS);
    int xr = tid >> 4, bl = (tid >> 3) & 1, cq = tid & 7;
    const ushortx* sAh = hxHI + ((size_t)(b0+bl)*NXS + k0 + xr)*DIMC + cq*8;
    const ushortx* sAl = hxLO + ((size_t)(b0+bl)*NXS + k0 + xr)*DIMC + cq*8;
    unsigned dAh = (unsigned)__cvta_generic_to_shared(&smA[0][0][xr][bl*32 + cq*4]);
    unsigned dAl = (unsigned)__cvta_generic_to_shared(&smA[1][0][xr][bl*32 + cq*4]);
    int rB = tid >> 1, chB = tid & 1;
    const ushortx* sBh = g_wbTHI + (size_t)rB*NXS + k0 + chB*8;
    const ushortx* sBl = g_wbTLO + (size_t)rB*NXS + k0 + chB*8;
    unsigned dBh = (unsigned)__cvta_generic_to_shared(&smB[0][0][rB][chB*4]);
    unsigned dBl = (unsigned)__cvta_generic_to_shared(&smB[1][0][rB][chB*4]);
    unsigned bAh = (unsigned)__cvta_generic_to_shared(&smA[0][0][0][0]);
    unsigned bAl = (unsigned)__cvta_generic_to_shared(&smA[1][0][0][0]);
    unsigned bBh = (unsigned)__cvta_generic_to_shared(&smB[0][0][0][0]);
    unsigned bBl = (unsigned)__cvta_generic_to_shared(&smB[1][0][0][0]);
    const unsigned ABUFO = 16*68*4, BBUFO = 128*48;
    unsigned loffT = ((lane & 7) + (lane >> 4)*8)*272 + ((lane >> 3) & 1)*16;
    unsigned loff  = (lane & 15)*48 + (lane >> 4)*16;
    float c[4][4][4] = {};
    CPA(dAh, sAh); CPA(dAl, sAl); CPA(dBh, sBh); CPA(dBl, sBl);
    CPC();
    for (int it = 0; it < NIT; it++){
        int cur = it & 1, nxt = cur ^ 1;
        if (it + 1 < NIT){
            CPA(dAh + nxt*ABUFO, sAh + (size_t)(it+1)*16*DIMC);
            CPA(dAl + nxt*ABUFO, sAl + (size_t)(it+1)*16*DIMC);
            CPA(dBh + nxt*BBUFO, sBh + (it+1)*16);
            CPA(dBl + nxt*BBUFO, sBl + (it+1)*16);
            CPC(); CPW1();
        } else CPW0();
        __syncthreads();
        unsigned Ah[4][4], Al[4][4], Bh[2][4], Bl[2][4];
        #pragma unroll
        for (int tm = 0; tm < 4; tm++){
            LDSM4T(Ah[tm], bAh + cur*ABUFO + loffT + (wm*64 + tm*16)*2);
            LDSM4T(Al[tm], bAl + cur*ABUFO + loffT + (wm*64 + tm*16)*2);
        }
        #pragma unroll
        for (int p = 0; p < 2; p++){
            LDSM4(Bh[p], bBh + cur*BBUFO + loff + (wn*32 + p*16)*48);
            LDSM4(Bl[p], bBl + cur*BBUFO + loff + (wn*32 + p*16)*48);
        }
        #pragma unroll
        for (int tm = 0; tm < 4; tm++)
            #pragma unroll
            for (int tn = 0; tn < 4; tn++){
                int p = tn >> 1, e = tn & 1;
                unsigned bh[2] = {Bh[p][e], Bh[p][e+2]};
                unsigned bl[2] = {Bl[p][e], Bl[p][e+2]};
                MMA(c[tm][tn], Ah[tm], bh);
                MMA(c[tm][tn], Al[tm], bh);
                MMA(c[tm][tn], Ah[tm], bl);
            }
        __syncthreads();
    }
    float* dst = &g_xhp[(size_t)blockIdx.y*(BSZ*DIMC*MODE)];
    #pragma unroll
    for (int tm = 0; tm < 4; tm++)
        #pragma unroll
        for (int tn = 0; tn < 4; tn++){
            int m = m0 + wm*64 + tm*16 + g;
            int n = wn*32 + tn*8 + t*2;
            *(float2*)&dst[(size_t)m*MODE + n]     = make_float2(c[tm][tn][0], c[tm][tn][1]);
            *(float2*)&dst[(size_t)(m+8)*MODE + n] = make_float2(c[tm][tn][2], c[tm][tn][3]);
        }
}
__global__ void k_reduce_xh(){
    int i = blockIdx.x * 256 + threadIdx.x;
    float s = 0.f;
    #pragma unroll
    for (int k = 0; k < XH_SPLITS; k++) s += g_xhp[(size_t)k*(BSZ*DIMC*MODE) + i];
    split2(s, g_xhHI[i], g_xhLO[i]);
}

// ===== xh1 (mma, R12 pipeline) =====
__global__ void __launch_bounds__(256) k_xh1_mma(){
    __shared__ __align__(16) unsigned smA[2][2][64][12];
    __shared__ __align__(16) unsigned smB[2][2][128][12];
    int tid = threadIdx.x, lane = tid & 31, wid = tid >> 5;
    int wm = wid >> 2, wn = wid & 3, g = lane >> 2, t = lane & 3;
    int b = blockIdx.x, j = blockIdx.y;
    unsigned loff = (lane & 15)*48 + (lane >> 4)*16;
    int aA = tid >> 7, rA = (tid >> 1) & 63, hA = tid & 1;
    const ushortx* srcA = (aA ? g_xhLO : g_xhHI) + ((size_t)b*DIMC + rA)*MODE + hA*8;
    unsigned dA = (unsigned)__cvta_generic_to_shared(&smA[aA][0][rA][hA*4]);
    unsigned bAh = (unsigned)__cvta_generic_to_shared(&smA[0][0][0][0]);
    unsigned bAl = (unsigned)__cvta_generic_to_shared(&smA[1][0][0][0]);
    unsigned bBh = (unsigned)__cvta_generic_to_shared(&smB[0][0][0][0]);
    unsigned bBl = (unsigned)__cvta_generic_to_shared(&smB[1][0][0][0]);
    const unsigned ABUFO = 64*12*4, BBUFO = 128*12*4;
    float c[2][4][4] = {};
    CPA(dA, srcA);
    #pragma unroll
    for (int rep = 0; rep < 2; rep++){
        int cid = tid + rep*256;
        int aB = cid >> 8, rBx = (cid >> 1) & 127, hB = cid & 1;
        const ushortx* srcB = (aB ? g_HjLO : g_HjHI) + ((size_t)j*MODE + rBx)*MODE + hB*8;
        CPA((unsigned)__cvta_generic_to_shared(&smB[aB][0][rBx][hB*4]), srcB);
    }
    CPC();
    for (int ks = 0; ks < 8; ks++){
        int cur = ks & 1, nxt = cur ^ 1;
        if (ks + 1 < 8){
            CPA(dA + nxt*ABUFO, srcA + (ks+1)*16);
            #pragma unroll
            for (int rep = 0; rep < 2; rep++){
                int cid = tid + rep*256;
                int aB = cid >> 8, rBx = (cid >> 1) & 127, hB = cid & 1;
                const ushortx* srcB = (aB ? g_HjLO : g_HjHI) + ((size_t)j*MODE + rBx)*MODE + hB*8;
                CPA((unsigned)__cvta_generic_to_shared(&smB[aB][0][rBx][hB*4]) + nxt*BBUFO,
                    srcB + (ks+1)*16);
            }
            CPC(); CPW1();
        } else CPW0();
        __syncthreads();
        unsigned offA = cur*ABUFO + loff, offB = cur*BBUFO + loff;
        unsigned Ah[2][4], Al[2][4], Bh[2][4], Bl[2][4];
        #pragma unroll
        for (int tm = 0; tm < 2; tm++){
            LDSM4(Ah[tm], bAh + offA + (wm*32 + tm*16)*48);
            LDSM4(Al[tm], bAl + offA + (wm*32 + tm*16)*48);
        }
        #pragma unroll
        for (int p = 0; p < 2; p++){
            LDSM4(Bh[p], bBh + offB + (wn*32 + p*16)*48);
            LDSM4(Bl[p], bBl + offB + (wn*32 + p*16)*48);
        }
        #pragma unroll
        for (int tm = 0; tm < 2; tm++)
            #pragma unroll
            for (int tn = 0; tn < 4; tn++){
                int p = tn >> 1, e = tn & 1;
                unsigned bh[2] = {Bh[p][e], Bh[p][e+2]};
                unsigned bl[2] = {Bl[p][e], Bl[p][e+2]};
                MMA(c[tm][tn], Ah[tm], bh);
                MMA(c[tm][tn], Al[tm], bh);
                MMA(c[tm][tn], Ah[tm], bl);
            }
        __syncthreads();
    }
    #pragma unroll
    for (int tm = 0; tm < 2; tm++)
        #pragma unroll
        for (int tn = 0; tn < 4; tn++){
            int m = wm*32 + tm*16 + g;
            int n = wn*32 + tn*8 + t*2;
            #pragma unroll
            for (int e = 0; e < 4; e++){
                int mm = m + (e >> 1)*8, nn = n + (e & 1);
                size_t o = ((size_t)b*MODE + nn)*(DIMC*NJ) + j*64 + mm;
                split2(c[tm][tn][e], g_x1THI[o], g_x1TLO[o]);
            }
        }
}
__global__ void k_WrT(const float* __restrict__ W_sp, int li){
    int idx = blockIdx.x * 256 + threadIdx.x;
    int p = idx & 1023, o = idx >> 10;
    int j = p >> 6, cc = p & 63;
    float v = W_sp[(((size_t)li*DIMC + cc)*DIMC + o)*NJ + j];
    split2(v, g_WrTTHI[idx], g_WrTTLO[idx]);
}
__global__ void __launch_bounds__(256) k_y_mma(){
    __shared__ __align__(16) unsigned smA[2][2][64][12];
    __shared__ __align__(16) unsigned smB[2][2][128][12];
    int tid = threadIdx.x, lane = tid & 31, wid = tid >> 5;
    int wm = wid >> 2, wn = wid & 3, g = lane >> 2, t = lane & 3;
    int b = blockIdx.x, sp = blockIdx.y;
    int p0 = sp * 256;
    unsigned loff = (lane & 15)*48 + (lane >> 4)*16;
    int aA = tid >> 7, rA = (tid >> 1) & 63, hA = tid & 1;
    const ushortx* srcA = (aA ? g_WrTTLO : g_WrTTHI) + (size_t)rA*(DIMC*NJ) + p0 + hA*8;
    unsigned dA = (unsigned)__cvta_generic_to_shared(&smA[aA][0][rA][hA*4]);
    unsigned bAh = (unsigned)__cvta_generic_to_shared(&smA[0][0][0][0]);
    unsigned bAl = (unsigned)__cvta_generic_to_shared(&smA[1][0][0][0]);
    unsigned bBh = (unsigned)__cvta_generic_to_shared(&smB[0][0][0][0]);
    unsigned bBl = (unsigned)__cvta_generic_to_shared(&smB[1][0][0][0]);
    const unsigned ABUFO = 64*12*4, BBUFO = 128*12*4;
    float c[2][4][4] = {};
    CPA(dA, srcA);
    #pragma unroll
    for (int rep = 0; rep < 2; rep++){
        int cid = tid + rep*256;
        int aB = cid >> 8, rBx = (cid >> 1) & 127, hB = cid & 1;
        const ushortx* srcB = (aB ? g_x1TLO : g_x1THI) + ((size_t)b*MODE + rBx)*(DIMC*NJ) + p0 + hB*8;
        CPA((unsigned)__cvta_generic_to_shared(&smB[aB][0][rBx][hB*4]), srcB);
    }
    CPC();
    for (int ks = 0; ks < 16; ks++){
        int cur = ks & 1, nxt = cur ^ 1;
        if (ks + 1 < 16){
            CPA(dA + nxt*ABUFO, srcA + (ks+1)*16);
            #pragma unroll
            for (int rep = 0; rep < 2; rep++){
                int cid = tid + rep*256;
                int aB = cid >> 8, rBx = (cid >> 1) & 127, hB = cid & 1;
                const ushortx* srcB = (aB ? g_x1TLO : g_x1THI) + ((size_t)b*MODE + rBx)*(DIMC*NJ) + p0 + hB*8;
                CPA((unsigned)__cvta_generic_to_shared(&smB[aB][0][rBx][hB*4]) + nxt*BBUFO,
                    srcB + (ks+1)*16);
            }
            CPC(); CPW1();
        } else CPW0();
        __syncthreads();
        unsigned offA = cur*ABUFO + loff, offB = cur*BBUFO + loff;
        unsigned Ah[2][4], Al[2][4], Bh[2][4], Bl[2][4];
        #pragma unroll
        for (int tm = 0; tm < 2; tm++){
            LDSM4(Ah[tm], bAh + offA + (wm*32 + tm*16)*48);
            LDSM4(Al[tm], bAl + offA + (wm*32 + tm*16)*48);
        }
        #pragma unroll
        for (int p = 0; p < 2; p++){
            LDSM4(Bh[p], bBh + offB + (wn*32 + p*16)*48);
            LDSM4(Bl[p], bBl + offB + (wn*32 + p*16)*48);
        }
        #pragma unroll
        for (int tm = 0; tm < 2; tm++)
            #pragma unroll
            for (int tn = 0; tn < 4; tn++){
                int p = tn >> 1, e = tn & 1;
                unsigned bh[2] = {Bh[p][e], Bh[p][e+2]};
                unsigned bl[2] = {Bl[p][e], Bl[p][e+2]};
                MMA(c[tm][tn], Ah[tm], bh);
                MMA(c[tm][tn], Al[tm], bh);
                MMA(c[tm][tn], Ah[tm], bl);
            }
        __syncthreads();
    }
    float* dst = &g_yp[(size_t)sp*(BSZ*DIMC*MODE)];
    #pragma unroll
    for (int tm = 0; tm < 2; tm++)
        #pragma unroll
        for (int tn = 0; tn < 4; tn++){
            int m = wm*32 + tm*16 + g;
            int n = wn*32 + tn*8 + t*2;
            *(float2*)&dst[((size_t)b*DIMC + m)*MODE + n]     = make_float2(c[tm][tn][0], c[tm][tn][1]);
            *(float2*)&dst[((size_t)b*DIMC + m + 8)*MODE + n] = make_float2(c[tm][tn][2], c[tm][tn][3]);
        }
}
__global__ void k_reduce_y(){
    int i = blockIdx.x * 256 + threadIdx.x;
    float s = 0.f;
    #pragma unroll
    for (int k = 0; k < Y_SPLITS; k++) s += g_yp[(size_t)k*(BSZ*DIMC*MODE) + i];
    split2(s, g_yHI[i], g_yLO[i]);
}

// ===== GEMM2 + tensorized fc1 (R12 pipeline; grid swapped for bases L2 reuse) =====
#define CSW 132
#define AHI_OFF 0
#define ALO_OFF 12288
#define BHI_OFF 24576
#define BLO_OFF 30720
#define ABUF 6144
#define BBUF 3072
#define FAHI 36864
#define FALO 43008
#define FBHI 49152
#define FBLO 55296
#define LSM_LAST 61440
#define LSM_MID  36864
__global__ void __launch_bounds__(256) k_L_mma(
    const ushortx* __restrict__ hxHI, const ushortx* __restrict__ hxLO,
    ushortx* __restrict__ hxoHI, ushortx* __restrict__ hxoLO,
    const float* __restrict__ biasv,
    const float* __restrict__ b1, const float* __restrict__ W2,
    const float* __restrict__ b2,
    float* __restrict__ out, int tail3, int is_last)
{
    extern __shared__ __align__(16) char pool[];
    float (*Csm)[CSW]  = (float(*)[CSW])pool;
    unsigned (*CsmU)[CSW] = (unsigned(*)[CSW])pool;
    int tid = threadIdx.x, lane = tid & 31, wid = tid >> 5;
    int wm = wid >> 2, wn = wid & 3, g = lane >> 2, t = lane & 3;
    int b = blockIdx.x;                 // swapped: co-resident blocks share x0
    int x0 = blockIdx.y * 128;
    int row = tid >> 1, ch = tid & 1;
    int nch = tail3 ? 8 : 12;
    unsigned sbase = (unsigned)__cvta_generic_to_shared(pool);
    unsigned dAhi = sbase + AHI_OFF + row*48 + ch*16;
    unsigned dAlo = dAhi + (ALO_OFF - AHI_OFF);
    unsigned bAhi = sbase + AHI_OFF, bAlo = sbase + ALO_OFF;
    unsigned bBhi = sbase + BHI_OFF, bBlo = sbase + BLO_OFF;
    int bhalf = tid >> 7, bo = (tid >> 1) & 63, bh = tid & 1;
    const ushortx* sBy = (bhalf ? g_yLO : g_yHI) + ((size_t)b*DIMC + bo)*MODE + bh*8;
    const ushortx* sBw = (bhalf ? g_WcLO : g_WcHI) + (size_t)bo*DIMC + bh*8;
    unsigned dB = sbase + (bhalf ? BLO_OFF : BHI_OFF) + bo*48 + bh*16;
    unsigned loff = (lane & 15)*48 + (lane >> 4)*16;
    float c[4][2][4] = {};
    CPA(dAhi, g_basesHI + (size_t)(x0+row)*MODE + ch*8);
    CPA(dAlo, g_basesLO + (size_t)(x0+row)*MODE + ch*8);
    CPA(dB, sBy);
    CPC();
    for (int chn = 0; chn < nch; chn++){
        int cur = chn & 1, nxt = cur ^ 1;
        if (chn + 1 < nch){
            int cn = chn + 1;
            if (cn < 8){
                CPA(dAhi + nxt*ABUF, g_basesHI + (size_t)(x0+row)*MODE + cn*16 + ch*8);
                CPA(dAlo + nxt*ABUF, g_basesLO + (size_t)(x0+row)*MODE + cn*16 + ch*8);
                CPA(dB + nxt*BBUF, sBy + cn*16);
            } else {
                CPA(dAhi + nxt*ABUF, hxHI + ((size_t)b*NXS + x0 + row)*DIMC + (cn-8)*16 + ch*8);
                CPA(dAlo + nxt*ABUF, hxLO + ((size_t)b*NXS + x0 + row)*DIMC + (cn-8)*16 + ch*8);
                CPA(dB + nxt*BBUF, sBw + (cn-8)*16);
            }
            CPC(); CPW1();
        } else CPW0();
        __syncthreads();
        unsigned offA = cur*ABUF + loff;
        unsigned offB = cur*BBUF + loff;
        unsigned Ah[4][4], Al[4][4], Bh[4], Bl[4];
        #pragma unroll
        for (int tm = 0; tm < 4; tm++){
            LDSM4(Ah[tm], bAhi + offA + (wm*64 + tm*16)*48);
            LDSM4(Al[tm], bAlo + offA + (wm*64 + tm*16)*48);
        }
        LDSM4(Bh, bBhi + offB + (wn*16)*48);
        LDSM4(Bl, bBlo + offB + (wn*16)*48);
        #pragma unroll
        for (int tm = 0; tm < 4; tm++)
            #pragma unroll
            for (int tn = 0; tn < 2; tn++){
                unsigned bhv[2] = {Bh[tn], Bh[tn+2]};
                unsigned blv[2] = {Bl[tn], Bl[tn+2]};
                MMA(c[tm][tn], Ah[tm], bhv);
                MMA(c[tm][tn], Al[tm], bhv);
                MMA(c[tm][tn], Ah[tm], blv);
            }
        __syncthreads();
    }
    #pragma unroll
    for (int tm = 0; tm < 4; tm++)
        #pragma unroll
        for (int tn = 0; tn < 2; tn++){
            int xr = wm*64 + tm*16 + g;
            int oc = wn*16 + tn*8 + t*2;
            Csm[oc][xr]     = c[tm][tn][0]; Csm[oc+1][xr]   = c[tm][tn][1];
            Csm[oc][xr+8]   = c[tm][tn][2]; Csm[oc+1][xr+8] = c[tm][tn][3];
        }
    __syncthreads();
    {
        int o = tid >> 2;
        float bias = tail3 ? g_bias0[o] : biasv[o];
        float w0 = 0.f, w1 = 0.f, w2c = 0.f;
        if (tail3){ w0 = g_Wc0T[o]; w1 = g_Wc0T[64+o]; w2c = g_Wc0T[128+o]; }
        #pragma unroll 4
        for (int j = 0; j < 32; j++){
            int xr = (tid & 3)*32 + j;
            float v = Csm[o][xr] + bias;
            if (tail3){
                int gx = x0 + xr;
                v += g_xT[((size_t)b*IN_DIM + 0)*NXS + gx]*w0
                   + g_xT[((size_t)b*IN_DIM + 1)*NXS + gx]*w1
                   + g_xT[((size_t)b*IN_DIM + 2)*NXS + gx]*w2c;
            }
            if (!is_last) CsmU[o][xr] = pk_split(gelu_f(v));
            else          Csm[o][xr] = v;
        }
    }
    __syncthreads();
    if (!is_last){
        for (int i = tid; i < 128*32; i += 256){
            int xx = i >> 5, cp = i & 31;
            unsigned u0 = CsmU[2*cp][xx], u1 = CsmU[2*cp+1][xx];
            unsigned hi = (u0 >> 16) | (u1 & 0xFFFF0000u);
            unsigned lo = (u0 & 0xFFFFu) | (u1 << 16);
            size_t base = ((size_t)b*NXS + x0 + xx)*DIMC;
            ((unsigned*)(hxoHI + base))[cp] = hi;
            ((unsigned*)(hxoLO + base))[cp] = lo;
        }
        return;
    }
    float c2[4][4][4] = {};
    int hh_ = tid & 1, xr_ = tid >> 1;
    for (int ks = 0; ks < 4; ks++){
        CPA(sbase + FBHI + row*48 + hh_*16, g_W1THI + row*64 + ks*16 + hh_*8);
        CPA(sbase + FBLO + row*48 + hh_*16, g_W1TLO + row*64 + ks*16 + hh_*8);
        CPC();
        {
            unsigned uh[4], ul[4];
            #pragma unroll
            for (int j = 0; j < 4; j++){
                ushortx h0,l0,h1,l1;
                split2(Csm[ks*16 + hh_*8 + 2*j][xr_], h0, l0);
                split2(Csm[ks*16 + hh_*8 + 2*j+1][xr_], h1, l1);
                uh[j] = (unsigned)h0 | ((unsigned)h1 << 16);
                ul[j] = (unsigned)l0 | ((unsigned)l1 << 16);
            }
            *(uint4*)(pool + FAHI + xr_*48 + hh_*16) = make_uint4(uh[0],uh[1],uh[2],uh[3]);
            *(uint4*)(pool + FALO + xr_*48 + hh_*16) = make_uint4(ul[0],ul[1],ul[2],ul[3]);
        }
        CPW0();
        __syncthreads();
        unsigned Ah[4][4], Al[4][4], Bh[2][4], Bl[2][4];
        #pragma unroll
        for (int tm = 0; tm < 4; tm++){
            LDSM4(Ah[tm], sbase + FAHI + loff + (wm*64 + tm*16)*48);
            LDSM4(Al[tm], sbase + FALO + loff + (wm*64 + tm*16)*48);
        }
        #pragma unroll
        for (int p = 0; p < 2; p++){
            LDSM4(Bh[p], sbase + FBHI + loff + (wn*32 + p*16)*48);
            LDSM4(Bl[p], sbase + FBLO + loff + (wn*32 + p*16)*48);
        }
        #pragma unroll
        for (int tm = 0; tm < 4; tm++)
            #pragma unroll
            for (int tn = 0; tn < 4; tn++){
                int p = tn >> 1, e = tn & 1;
                unsigned bh[2] = {Bh[p][e], Bh[p][e+2]};
                unsigned bl[2] = {Bl[p][e], Bl[p][e+2]};
                MMA(c2[tm][tn], Ah[tm], bh);
                MMA(c2[tm][tn], Al[tm], bh);
                MMA(c2[tm][tn], Ah[tm], bl);
            }
        __syncthreads();
    }
    float part[4][2] = {};
    #pragma unroll
    for (int tn = 0; tn < 4; tn++){
        int f0 = wn*32 + tn*8 + t*2;
        float b10 = b1[f0], b11 = b1[f0+1];
        float w20 = W2[f0], w21 = W2[f0+1];
        #pragma unroll
        for (int tm = 0; tm < 4; tm++){
            part[tm][0] += gelu_f(c2[tm][tn][0]+b10)*w20 + gelu_f(c2[tm][tn][1]+b11)*w21;
            part[tm][1] += gelu_f(c2[tm][tn][2]+b10)*w20 + gelu_f(c2[tm][tn][3]+b11)*w21;
        }
    }
    float (*red)[16] = (float(*)[16])(pool + FAHI);
    #pragma unroll
    for (int tm = 0; tm < 4; tm++){
        int xr0 = wm*64 + tm*16 + g;
        red[xr0][wn*4 + t]   = part[tm][0];
        red[xr0+8][wn*4 + t] = part[tm][1];
    }
    __syncthreads();
    if (tid < 128){
        float s = b2[0];
        #pragma unroll
        for (int k = 0; k < 16; k++) s += red[tid][k];
        out[(size_t)b*NXS + x0 + tid] = s;
    }
}

// ---------------------------------------------------------------------------
extern "C" void kernel_launch(void* const* d_in, const int* in_sizes, int n_in,
                              void* d_out, int out_size){
    (void)in_sizes; (void)n_in; (void)out_size;
    const float* x      = (const float*)d_in[0];
    const float* bases  = (const float*)d_in[1];
    const float* wbases = (const float*)d_in[2];
    const float* product= (const float*)d_in[3];
    const float* Do     = (const float*)d_in[4];
    const float* Di     = (const float*)d_in[5];
    const float* A      = (const float*)d_in[6];
    const float* Bm     = (const float*)d_in[7];
    const float* W_sp   = (const float*)d_in[8];
    const float* W_conv = (const float*)d_in[9];
    const float* b_conv = (const float*)d_in[10];
    const float* W0     = (const float*)d_in[11];
    const float* b0     = (const float*)d_in[12];
    const float* W1     = (const float*)d_in[13];
    const float* b1     = (const float*)d_in[14];
    const float* W2     = (const float*)d_in[15];
    const float* b2     = (const float*)d_in[16];
    float* out = (float*)d_out;

    cudaFuncSetAttribute(k_L_mma, cudaFuncAttributeMaxDynamicSharedMemorySize, LSM_LAST);

    ushortx *hxHa,*hxLa,*hxHb,*hxLb;
    cudaGetSymbolAddress((void**)&hxHa, g_hxHIa);
    cudaGetSymbolAddress((void**)&hxLa, g_hxLOa);
    cudaGetSymbolAddress((void**)&hxHb, g_hxHIb);
    cudaGetSymbolAddress((void**)&hxLb, g_hxLOb);

    k_basesP<<<(NXS*MODE)/256, 256>>>(bases);
    k_wbTP<<<dim3(NXS/32, MODE/32), dim3(32,8)>>>(wbases);
    k_W1TP<<<(FCD*DIMC)/256, 256>>>(W1);
    k_buildH<<<dim3(NJ, MODE), MODE>>>(Do, Di, product, A, Bm);
    k_xT<<<(BSZ*NXS*IN_DIM)/256, 256>>>(x);
    k_prep0<<<1, DIMC>>>(W_conv, W0, b0, b_conv);

    // ---- layer 0 ----
    k_T<<<dim3(BSZ, T_SPLITS), MODE>>>(wbases);
    k_xh0<<<BSZ, 256>>>(W0, b0);
    k_xh1_mma<<<dim3(BSZ, NJ), 256>>>();
    k_WrT<<<(DIMC*DIMC*NJ)/256, 256>>>(W_sp, 0);
    k_y_mma<<<dim3(BSZ, Y_SPLITS), 256>>>();
    k_reduce_y<<<(BSZ*DIMC*MODE)/256, 256>>>();
    k_L_mma<<<dim3(BSZ, NXS/128), 256, LSM_MID>>>(hxHa, hxLa, hxHa, hxLa,
                                                  nullptr,
                                                  b1, W2, b2, out, 1, 0);
    // ---- layers 1,2 ----
    const ushortx *hxH = hxHa, *hxL = hxLa;
    ushortx *hxHo = hxHb, *hxLo = hxLb;
    for (int li = 1; li < N_LAYERS; li++){
        int last = (li == N_LAYERS-1) ? 1 : 0;
        k_xh_mma<<<dim3((BSZ*DIMC)/128, XH_SPLITS), 256>>>(hxH, hxL);
        k_reduce_xh<<<(BSZ*DIMC*MODE)/256, 256>>>();
        k_xh1_mma<<<dim3(BSZ, NJ), 256>>>();
        k_WrT<<<(DIMC*DIMC*NJ)/256, 256>>>(W_sp, li);
        k_y_mma<<<dim3(BSZ, Y_SPLITS), 256>>>();
        k_reduce_y<<<(BSZ*DIMC*MODE)/256, 256>>>();
        k_WcP<<<(DIMC*DIMC)/256, 256>>>(W_conv, li);
        k_L_mma<<<dim3(BSZ, NXS/128), 256, last ? LSM_LAST : LSM_MID>>>(
                                             hxH, hxL, hxHo, hxLo,
                                             &b_conv[(size_t)li*DIMC],
                                             b1, W2, b2, out, 0, last);
        const ushortx* t3 = hxH; hxH = hxHo; hxHo = (ushortx*)t3;
        const ushortx* t4 = hxL; hxL = hxLo; hxLo = (ushortx*)t4;
    }
}

// round 15
// speedup vs baseline: 1.0822x; 1.0013x over previous
#include <cuda_runtime.h>
#include <cuda_bf16.h>
#include <math.h>
#include <stdint.h>

#define BSZ 32
#define NXS 16384
#define IN_DIM 3
#define DIMC 64
#define NJ 16
#define MODE 128
#define RANKR 4
#define FCD 128
#define N_LAYERS 3
#define XH_SPLITS 8
#define Y_SPLITS 4
#define T_SPLITS 8

typedef unsigned short ushortx;

__device__ ushortx g_hxHIa[(size_t)BSZ*NXS*DIMC];
__device__ ushortx g_hxLOa[(size_t)BSZ*NXS*DIMC];
__device__ ushortx g_hxHIb[(size_t)BSZ*NXS*DIMC];
__device__ ushortx g_hxLOb[(size_t)BSZ*NXS*DIMC];
__device__ ushortx g_wbTHI[(size_t)MODE*NXS];
__device__ ushortx g_wbTLO[(size_t)MODE*NXS];
__device__ ushortx g_basesHI[(size_t)NXS*MODE];
__device__ ushortx g_basesLO[(size_t)NXS*MODE];
__device__ ushortx g_W1THI[FCD*DIMC];
__device__ ushortx g_W1TLO[FCD*DIMC];
__device__ ushortx g_HjHI[NJ*MODE*MODE];
__device__ ushortx g_HjLO[NJ*MODE*MODE];
__device__ ushortx g_xhHI[BSZ*DIMC*MODE];
__device__ ushortx g_xhLO[BSZ*DIMC*MODE];
__device__ ushortx g_x1THI[(size_t)BSZ*MODE*(DIMC*NJ)];
__device__ ushortx g_x1TLO[(size_t)BSZ*MODE*(DIMC*NJ)];
__device__ ushortx g_WrTTHI[DIMC*DIMC*NJ];
__device__ ushortx g_WrTTLO[DIMC*DIMC*NJ];
__device__ ushortx g_yHI[BSZ*DIMC*MODE];
__device__ ushortx g_yLO[BSZ*DIMC*MODE];
__device__ ushortx g_WcHI[DIMC*DIMC];
__device__ ushortx g_WcLO[DIMC*DIMC];
__device__ float g_xT[BSZ*IN_DIM*NXS];
__device__ float g_xhp[XH_SPLITS*BSZ*DIMC*MODE];
__device__ float g_yp [Y_SPLITS*BSZ*DIMC*MODE];
__device__ float g_Tp [T_SPLITS*BSZ*4*MODE];
__device__ float g_Wc0T[IN_DIM*DIMC];
__device__ float g_bias0[DIMC];

__device__ __forceinline__ float gelu_f(float v){
    return 0.5f * v * (1.0f + erff(v * 0.70710678118654752440f));
}
__device__ __forceinline__ void split2(float x, ushortx& hi, ushortx& lo){
    __nv_bfloat16 h = __float2bfloat16(x);
    hi = __bfloat16_as_ushort(h);
    lo = __bfloat16_as_ushort(__float2bfloat16(x - __bfloat162float(h)));
}
__device__ __forceinline__ unsigned pk_split(float x){
    ushortx hi, lo; split2(x, hi, lo);
    return ((unsigned)hi << 16) | (unsigned)lo;
}
#define MMA(c,a,b) asm volatile( \
    "mma.sync.aligned.m16n8k16.row.col.f32.bf16.bf16.f32 " \
    "{%0,%1,%2,%3}, {%4,%5,%6,%7}, {%8,%9}, {%0,%1,%2,%3};" \
    : "+f"((c)[0]), "+f"((c)[1]), "+f"((c)[2]), "+f"((c)[3]) \
    : "r"((a)[0]), "r"((a)[1]), "r"((a)[2]), "r"((a)[3]), "r"((b)[0]), "r"((b)[1]))
#define LDSM4(f,addr) asm volatile( \
    "ldmatrix.sync.aligned.m8n8.x4.shared.b16 {%0,%1,%2,%3}, [%4];" \
    : "=r"((f)[0]), "=r"((f)[1]), "=r"((f)[2]), "=r"((f)[3]) : "r"(addr))
#define LDSM4T(f,addr) asm volatile( \
    "ldmatrix.sync.aligned.m8n8.x4.trans.shared.b16 {%0,%1,%2,%3}, [%4];" \
    : "=r"((f)[0]), "=r"((f)[1]), "=r"((f)[2]), "=r"((f)[3]) : "r"(addr))
#define CPA(dst,src) asm volatile("cp.async.cg.shared.global [%0], [%1], 16;" :: "r"(dst), "l"(src))
#define CPC() asm volatile("cp.async.commit_group;" ::: "memory")
#define CPW1() asm volatile("cp.async.wait_group 1;" ::: "memory")
#define CPW0() asm volatile("cp.async.wait_group 0;" ::: "memory")

// ---------------- prep ----------------
__global__ void k_xT(const float* __restrict__ x){
    int i = blockIdx.x * 256 + threadIdx.x;
    int d = i % 3, t = i / 3;
    g_xT[((size_t)(t >> 14)*IN_DIM + d)*NXS + (t & (NXS-1))] = x[i];
}
__global__ void k_basesP(const float* __restrict__ bases){
    int i = blockIdx.x * 256 + threadIdx.x;
    split2(bases[i], g_basesHI[i], g_basesLO[i]);
}
__global__ void k_wbTP(const float* __restrict__ wb){
    __shared__ float t[32][33];
    int x0 = blockIdx.x * 32, k0 = blockIdx.y * 32;
    for (int i = threadIdx.y; i < 32; i += 8)
        t[i][threadIdx.x] = wb[(size_t)(x0 + i)*MODE + k0 + threadIdx.x];
    __syncthreads();
    for (int i = threadIdx.y; i < 32; i += 8){
        size_t o = (size_t)(k0 + i)*NXS + x0 + threadIdx.x;
        split2(t[threadIdx.x][i], g_wbTHI[o], g_wbTLO[o]);
    }
}
__global__ void k_W1TP(const float* __restrict__ W1){
    int i = blockIdx.x * 256 + threadIdx.x;
    int f = i >> 6, c = i & 63;
    split2(W1[c*FCD + f], g_W1THI[i], g_W1TLO[i]);
}
__global__ void k_WcP(const float* __restrict__ W_conv, int li){
    int i = blockIdx.x * 256 + threadIdx.x;
    split2(W_conv[(size_t)li*DIMC*DIMC + i], g_WcHI[i], g_WcLO[i]);
}
__global__ void k_buildH(const float* __restrict__ Do, const float* __restrict__ Di,
                         const float* __restrict__ pr, const float* __restrict__ A,
                         const float* __restrict__ Bm){
    int j = blockIdx.x, k = blockIdx.y, l = threadIdx.x;
    float s = Do[j*MODE + k] * Di[j*MODE + l] * pr[k*MODE + l];
    #pragma unroll
    for (int r = 0; r < RANKR; r++)
        s += A[(j*RANKR + r)*MODE + k] * Bm[(j*RANKR + r)*MODE + l];
    size_t o = ((size_t)j*MODE + k)*MODE + l;
    split2(s, g_HjHI[o], g_HjLO[o]);
}
__global__ void k_prep0(const float* __restrict__ W_conv, const float* __restrict__ W0,
                        const float* __restrict__ b0, const float* __restrict__ b_conv){
    int o = threadIdx.x;
    float w0s = 0.f, w1s = 0.f, w2s = 0.f, bb = b_conv[o];
    for (int c = 0; c < DIMC; c++){
        float wc = W_conv[o*DIMC + c];
        w0s += wc*W0[c]; w1s += wc*W0[DIMC+c]; w2s += wc*W0[2*DIMC+c];
        bb  += wc*b0[c];
    }
    g_Wc0T[o] = w0s; g_Wc0T[64+o] = w1s; g_Wc0T[128+o] = w2s; g_bias0[o] = bb;
}
__global__ void k_T(const float* __restrict__ wbases){
    int b = blockIdx.x, s = blockIdx.y;
    int x0 = s * (NXS / T_SPLITS);
    int k = threadIdx.x;
    __shared__ float xs[3][128];
    float a0=0.f, a1=0.f, a2=0.f, a3=0.f;
    for (int xt = 0; xt < (NXS/T_SPLITS)/128; xt++){
        __syncthreads();
        xs[0][k] = g_xT[((size_t)b*IN_DIM + 0)*NXS + x0 + xt*128 + k];
        xs[1][k] = g_xT[((size_t)b*IN_DIM + 1)*NXS + x0 + xt*128 + k];
        xs[2][k] = g_xT[((size_t)b*IN_DIM + 2)*NXS + x0 + xt*128 + k];
        __syncthreads();
        #pragma unroll 8
        for (int xi = 0; xi < 128; xi++){
            float w = wbases[(size_t)(x0 + xt*128 + xi)*MODE + k];
            a0 += xs[0][xi]*w; a1 += xs[1][xi]*w; a2 += xs[2][xi]*w; a3 += w;
        }
    }
    size_t base = (((size_t)s*BSZ + b)*4)*MODE + k;
    g_Tp[base] = a0; g_Tp[base+MODE] = a1; g_Tp[base+2*MODE] = a2; g_Tp[base+3*MODE] = a3;
}
__global__ void k_xh0(const float* __restrict__ W0, const float* __restrict__ b0){
    int b = blockIdx.x;
    __shared__ float Ts[4][128];
    int tid = threadIdx.x;
    for (int e = tid; e < 4*MODE; e += 256){
        int d = e >> 7, k = e & 127;
        float s = 0.f;
        #pragma unroll
        for (int s8 = 0; s8 < T_SPLITS; s8++)
            s += g_Tp[(((size_t)s8*BSZ + b)*4 + d)*MODE + k];
        Ts[d][k] = s;
    }
    __syncthreads();
    for (int o = tid; o < DIMC*MODE; o += 256){
        int c = o >> 7, k = o & 127;
        float v = W0[c]*Ts[0][k] + W0[DIMC+c]*Ts[1][k] + W0[2*DIMC+c]*Ts[2][k] + b0[c]*Ts[3][k];
        size_t idx = (size_t)b*DIMC*MODE + o;
        split2(v, g_xhHI[idx], g_xhLO[idx]);
    }
}

// ===== GEMM1 (R12 pipeline: CPW1) =====
__global__ void __launch_bounds__(256) k_xh_mma(const ushortx* __restrict__ hxHI,
                                                const ushortx* __restrict__ hxLO){
    __shared__ __align__(16) unsigned smA[2][2][16][68];
    __shared__ __align__(16) unsigned smB[2][2][128][12];
    const int NIT = (NXS/XH_SPLITS)/16;
    int tid = threadIdx.x, lane = tid & 31, wid = tid >> 5;
    int wm = wid >> 2, wn = wid & 3, g = lane >> 2, t = lane & 3;
    int m0 = blockIdx.x * 128, b0 = blockIdx.x * 2;
    int k0 = blockIdx.y * (NXS / XH_SPLITS);
    int xr = tid >> 4, bl = (tid >> 3) & 1, cq = tid & 7;
    const ushortx* sAh = hxHI + ((size_t)(b0+bl)*NXS + k0 + xr)*DIMC + cq*8;
    const ushortx* sAl = hxLO + ((size_t)(b0+bl)*NXS + k0 + xr)*DIMC + cq*8;
    unsigned dAh = (unsigned)__cvta_generic_to_shared(&smA[0][0][xr][bl*32 + cq*4]);
    unsigned dAl = (unsigned)__cvta_generic_to_shared(&smA[1][0][xr][bl*32 + cq*4]);
    int rB = tid >> 1, chB = tid & 1;
    const ushortx* sBh = g_wbTHI + (size_t)rB*NXS + k0 + chB*8;
    const ushortx* sBl = g_wbTLO + (size_t)rB*NXS + k0 + chB*8;
    unsigned dBh = (unsigned)__cvta_generic_to_shared(&smB[0][0][rB][chB*4]);
    unsigned dBl = (unsigned)__cvta_generic_to_shared(&smB[1][0][rB][chB*4]);
    unsigned bAh = (unsigned)__cvta_generic_to_shared(&smA[0][0][0][0]);
    unsigned bAl = (unsigned)__cvta_generic_to_shared(&smA[1][0][0][0]);
    unsigned bBh = (unsigned)__cvta_generic_to_shared(&smB[0][0][0][0]);
    unsigned bBl = (unsigned)__cvta_generic_to_shared(&smB[1][0][0][0]);
    const unsigned ABUFO = 16*68*4, BBUFO = 128*48;
    unsigned loffT = ((lane & 7) + (lane >> 4)*8)*272 + ((lane >> 3) & 1)*16;
    unsigned loff  = (lane & 15)*48 + (lane >> 4)*16;
    float c[4][4][4] = {};
    CPA(dAh, sAh); CPA(dAl, sAl); CPA(dBh, sBh); CPA(dBl, sBl);
    CPC();
    for (int it = 0; it < NIT; it++){
        int cur = it & 1, nxt = cur ^ 1;
        if (it + 1 < NIT){
            CPA(dAh + nxt*ABUFO, sAh + (size_t)(it+1)*16*DIMC);
            CPA(dAl + nxt*ABUFO, sAl + (size_t)(it+1)*16*DIMC);
            CPA(dBh + nxt*BBUFO, sBh + (it+1)*16);
            CPA(dBl + nxt*BBUFO, sBl + (it+1)*16);
            CPC(); CPW1();
        } else CPW0();
        __syncthreads();
        unsigned Ah[4][4], Al[4][4], Bh[2][4], Bl[2][4];
        #pragma unroll
        for (int tm = 0; tm < 4; tm++){
            LDSM4T(Ah[tm], bAh + cur*ABUFO + loffT + (wm*64 + tm*16)*2);
            LDSM4T(Al[tm], bAl + cur*ABUFO + loffT + (wm*64 + tm*16)*2);
        }
        #pragma unroll
        for (int p = 0; p < 2; p++){
            LDSM4(Bh[p], bBh + cur*BBUFO + loff + (wn*32 + p*16)*48);
            LDSM4(Bl[p], bBl + cur*BBUFO + loff + (wn*32 + p*16)*48);
        }
        #pragma unroll
        for (int tm = 0; tm < 4; tm++)
            #pragma unroll
            for (int tn = 0; tn < 4; tn++){
                int p = tn >> 1, e = tn & 1;
                unsigned bh[2] = {Bh[p][e], Bh[p][e+2]};
                unsigned bl[2] = {Bl[p][e], Bl[p][e+2]};
                MMA(c[tm][tn], Ah[tm], bh);
                MMA(c[tm][tn], Al[tm], bh);
                MMA(c[tm][tn], Ah[tm], bl);
            }
        __syncthreads();
    }
    float* dst = &g_xhp[(size_t)blockIdx.y*(BSZ*DIMC*MODE)];
    #pragma unroll
    for (int tm = 0; tm < 4; tm++)
        #pragma unroll
        for (int tn = 0; tn < 4; tn++){
            int m = m0 + wm*64 + tm*16 + g;
            int n = wn*32 + tn*8 + t*2;
            *(float2*)&dst[(size_t)m*MODE + n]     = make_float2(c[tm][tn][0], c[tm][tn][1]);
            *(float2*)&dst[(size_t)(m+8)*MODE + n] = make_float2(c[tm][tn][2], c[tm][tn][3]);
        }
}
__global__ void k_reduce_xh(){
    int i = blockIdx.x * 256 + threadIdx.x;
    float s = 0.f;
    #pragma unroll
    for (int k = 0; k < XH_SPLITS; k++) s += g_xhp[(size_t)k*(BSZ*DIMC*MODE) + i];
    split2(s, g_xhHI[i], g_xhLO[i]);
}

// ===== xh1 (mma, R12 pipeline) =====
__global__ void __launch_bounds__(256) k_xh1_mma(){
    __shared__ __align__(16) unsigned smA[2][2][64][12];
    __shared__ __align__(16) unsigned smB[2][2][128][12];
    int tid = threadIdx.x, lane = tid & 31, wid = tid >> 5;
    int wm = wid >> 2, wn = wid & 3, g = lane >> 2, t = lane & 3;
    int b = blockIdx.x, j = blockIdx.y;
    unsigned loff = (lane & 15)*48 + (lane >> 4)*16;
    int aA = tid >> 7, rA = (tid >> 1) & 63, hA = tid & 1;
    const ushortx* srcA = (aA ? g_xhLO : g_xhHI) + ((size_t)b*DIMC + rA)*MODE + hA*8;
    unsigned dA = (unsigned)__cvta_generic_to_shared(&smA[aA][0][rA][hA*4]);
    unsigned bAh = (unsigned)__cvta_generic_to_shared(&smA[0][0][0][0]);
    unsigned bAl = (unsigned)__cvta_generic_to_shared(&smA[1][0][0][0]);
    unsigned bBh = (unsigned)__cvta_generic_to_shared(&smB[0][0][0][0]);
    unsigned bBl = (unsigned)__cvta_generic_to_shared(&smB[1][0][0][0]);
    const unsigned ABUFO = 64*12*4, BBUFO = 128*12*4;
    float c[2][4][4] = {};
    CPA(dA, srcA);
    #pragma unroll
    for (int rep = 0; rep < 2; rep++){
        int cid = tid + rep*256;
        int aB = cid >> 8, rBx = (cid >> 1) & 127, hB = cid & 1;
        const ushortx* srcB = (aB ? g_HjLO : g_HjHI) + ((size_t)j*MODE + rBx)*MODE + hB*8;
        CPA((unsigned)__cvta_generic_to_shared(&smB[aB][0][rBx][hB*4]), srcB);
    }
    CPC();
    for (int ks = 0; ks < 8; ks++){
        int cur = ks & 1, nxt = cur ^ 1;
        if (ks + 1 < 8){
            CPA(dA + nxt*ABUFO, srcA + (ks+1)*16);
            #pragma unroll
            for (int rep = 0; rep < 2; rep++){
                int cid = tid + rep*256;
                int aB = cid >> 8, rBx = (cid >> 1) & 127, hB = cid & 1;
                const ushortx* srcB = (aB ? g_HjLO : g_HjHI) + ((size_t)j*MODE + rBx)*MODE + hB*8;
                CPA((unsigned)__cvta_generic_to_shared(&smB[aB][0][rBx][hB*4]) + nxt*BBUFO,
                    srcB + (ks+1)*16);
            }
            CPC(); CPW1();
        } else CPW0();
        __syncthreads();
        unsigned offA = cur*ABUFO + loff, offB = cur*BBUFO + loff;
        unsigned Ah[2][4], Al[2][4], Bh[2][4], Bl[2][4];
        #pragma unroll
        for (int tm = 0; tm < 2; tm++){
            LDSM4(Ah[tm], bAh + offA + (wm*32 + tm*16)*48);
            LDSM4(Al[tm], bAl + offA + (wm*32 + tm*16)*48);
        }
        #pragma unroll
        for (int p = 0; p < 2; p++){
            LDSM4(Bh[p], bBh + offB + (wn*32 + p*16)*48);
            LDSM4(Bl[p], bBl + offB + (wn*32 + p*16)*48);
        }
        #pragma unroll
        for (int tm = 0; tm < 2; tm++)
            #pragma unroll
            for (int tn = 0; tn < 4; tn++){
                int p = tn >> 1, e = tn & 1;
                unsigned bh[2] = {Bh[p][e], Bh[p][e+2]};
                unsigned bl[2] = {Bl[p][e], Bl[p][e+2]};
                MMA(c[tm][tn], Ah[tm], bh);
                MMA(c[tm][tn], Al[tm], bh);
                MMA(c[tm][tn], Ah[tm], bl);
            }
        __syncthreads();
    }
    #pragma unroll
    for (int tm = 0; tm < 2; tm++)
        #pragma unroll
        for (int tn = 0; tn < 4; tn++){
            int m = wm*32 + tm*16 + g;
            int n = wn*32 + tn*8 + t*2;
            #pragma unroll
            for (int e = 0; e < 4; e++){
                int mm = m + (e >> 1)*8, nn = n + (e & 1);
                size_t o = ((size_t)b*MODE + nn)*(DIMC*NJ) + j*64 + mm;
                split2(c[tm][tn][e], g_x1THI[o], g_x1TLO[o]);
            }
        }
}
__global__ void k_WrT(const float* __restrict__ W_sp, int li){
    int idx = blockIdx.x * 256 + threadIdx.x;
    int p = idx & 1023, o = idx >> 10;
    int j = p >> 6, cc = p & 63;
    float v = W_sp[(((size_t)li*DIMC + cc)*DIMC + o)*NJ + j];
    split2(v, g_WrTTHI[idx], g_WrTTLO[idx]);
}
__global__ void __launch_bounds__(256) k_y_mma(){
    __shared__ __align__(16) unsigned smA[2][2][64][12];
    __shared__ __align__(16) unsigned smB[2][2][128][12];
    int tid = threadIdx.x, lane = tid & 31, wid = tid >> 5;
    int wm = wid >> 2, wn = wid & 3, g = lane >> 2, t = lane & 3;
    int b = blockIdx.x, sp = blockIdx.y;
    int p0 = sp * 256;
    unsigned loff = (lane & 15)*48 + (lane >> 4)*16;
    int aA = tid >> 7, rA = (tid >> 1) & 63, hA = tid & 1;
    const ushortx* srcA = (aA ? g_WrTTLO : g_WrTTHI) + (size_t)rA*(DIMC*NJ) + p0 + hA*8;
    unsigned dA = (unsigned)__cvta_generic_to_shared(&smA[aA][0][rA][hA*4]);
    unsigned bAh = (unsigned)__cvta_generic_to_shared(&smA[0][0][0][0]);
    unsigned bAl = (unsigned)__cvta_generic_to_shared(&smA[1][0][0][0]);
    unsigned bBh = (unsigned)__cvta_generic_to_shared(&smB[0][0][0][0]);
    unsigned bBl = (unsigned)__cvta_generic_to_shared(&smB[1][0][0][0]);
    const unsigned ABUFO = 64*12*4, BBUFO = 128*12*4;
    float c[2][4][4] = {};
    CPA(dA, srcA);
    #pragma unroll
    for (int rep = 0; rep < 2; rep++){
        int cid = tid + rep*256;
        int aB = cid >> 8, rBx = (cid >> 1) & 127, hB = cid & 1;
        const ushortx* srcB = (aB ? g_x1TLO : g_x1THI) + ((size_t)b*MODE + rBx)*(DIMC*NJ) + p0 + hB*8;
        CPA((unsigned)__cvta_generic_to_shared(&smB[aB][0][rBx][hB*4]), srcB);
    }
    CPC();
    for (int ks = 0; ks < 16; ks++){
        int cur = ks & 1, nxt = cur ^ 1;
        if (ks + 1 < 16){
            CPA(dA + nxt*ABUFO, srcA + (ks+1)*16);
            #pragma unroll
            for (int rep = 0; rep < 2; rep++){
                int cid = tid + rep*256;
                int aB = cid >> 8, rBx = (cid >> 1) & 127, hB = cid & 1;
                const ushortx* srcB = (aB ? g_x1TLO : g_x1THI) + ((size_t)b*MODE + rBx)*(DIMC*NJ) + p0 + hB*8;
                CPA((unsigned)__cvta_generic_to_shared(&smB[aB][0][rBx][hB*4]) + nxt*BBUFO,
                    srcB + (ks+1)*16);
            }
            CPC(); CPW1();
        } else CPW0();
        __syncthreads();
        unsigned offA = cur*ABUFO + loff, offB = cur*BBUFO + loff;
        unsigned Ah[2][4], Al[2][4], Bh[2][4], Bl[2][4];
        #pragma unroll
        for (int tm = 0; tm < 2; tm++){
            LDSM4(Ah[tm], bAh + offA + (wm*32 + tm*16)*48);
            LDSM4(Al[tm], bAl + offA + (wm*32 + tm*16)*48);
        }
        #pragma unroll
        for (int p = 0; p < 2; p++){
            LDSM4(Bh[p], bBh + offB + (wn*32 + p*16)*48);
            LDSM4(Bl[p], bBl + offB + (wn*32 + p*16)*48);
        }
        #pragma unroll
        for (int tm = 0; tm < 2; tm++)
            #pragma unroll
            for (int tn = 0; tn < 4; tn++){
                int p = tn >> 1, e = tn & 1;
                unsigned bh[2] = {Bh[p][e], Bh[p][e+2]};
                unsigned bl[2] = {Bl[p][e], Bl[p][e+2]};
                MMA(c[tm][tn], Ah[tm], bh);
                MMA(c[tm][tn], Al[tm], bh);
                MMA(c[tm][tn], Ah[tm], bl);
            }
        __syncthreads();
    }
    float* dst = &g_yp[(size_t)sp*(BSZ*DIMC*MODE)];
    #pragma unroll
    for (int tm = 0; tm < 2; tm++)
        #pragma unroll
        for (int tn = 0; tn < 4; tn++){
            int m = wm*32 + tm*16 + g;
            int n = wn*32 + tn*8 + t*2;
            *(float2*)&dst[((size_t)b*DIMC + m)*MODE + n]     = make_float2(c[tm][tn][0], c[tm][tn][1]);
            *(float2*)&dst[((size_t)b*DIMC + m + 8)*MODE + n] = make_float2(c[tm][tn][2], c[tm][tn][3]);
        }
}
__global__ void k_reduce_y(){
    int i = blockIdx.x * 256 + threadIdx.x;
    float s = 0.f;
    #pragma unroll
    for (int k = 0; k < Y_SPLITS; k++) s += g_yp[(size_t)k*(BSZ*DIMC*MODE) + i];
    split2(s, g_yHI[i], g_yLO[i]);
}

// ===== GEMM2 + tensorized fc1 (4x2 warp layout in main GEMM) =====
#define CSW 132
#define AHI_OFF 0
#define ALO_OFF 12288
#define BHI_OFF 24576
#define BLO_OFF 30720
#define ABUF 6144
#define BBUF 3072
#define FAHI 36864
#define FALO 43008
#define FBHI 49152
#define FBLO 55296
#define LSM_LAST 61440
#define LSM_MID  36864
__global__ void __launch_bounds__(256) k_L_mma(
    const ushortx* __restrict__ hxHI, const ushortx* __restrict__ hxLO,
    ushortx* __restrict__ hxoHI, ushortx* __restrict__ hxoLO,
    const float* __restrict__ biasv,
    const float* __restrict__ b1, const float* __restrict__ W2,
    const float* __restrict__ b2,
    float* __restrict__ out, int tail3, int is_last)
{
    extern __shared__ __align__(16) char pool[];
    float (*Csm)[CSW]  = (float(*)[CSW])pool;
    unsigned (*CsmU)[CSW] = (unsigned(*)[CSW])pool;
    int tid = threadIdx.x, lane = tid & 31, wid = tid >> 5;
    int wm = wid >> 2, wn = wid & 3, g = lane >> 2, t = lane & 3;   // fc1 epilogue layout
    int wmA = wid >> 1, wnA = wid & 1;                              // main GEMM layout 4x2
    int b = blockIdx.x;
    int x0 = blockIdx.y * 128;
    int row = tid >> 1, ch = tid & 1;
    int nch = tail3 ? 8 : 12;
    unsigned sbase = (unsigned)__cvta_generic_to_shared(pool);
    unsigned dAhi = sbase + AHI_OFF + row*48 + ch*16;
    unsigned dAlo = dAhi + (ALO_OFF - AHI_OFF);
    unsigned bAhi = sbase + AHI_OFF, bAlo = sbase + ALO_OFF;
    unsigned bBhi = sbase + BHI_OFF, bBlo = sbase + BLO_OFF;
    int bhalf = tid >> 7, bo = (tid >> 1) & 63, bh = tid & 1;
    const ushortx* sBy = (bhalf ? g_yLO : g_yHI) + ((size_t)b*DIMC + bo)*MODE + bh*8;
    const ushortx* sBw = (bhalf ? g_WcLO : g_WcHI) + (size_t)bo*DIMC + bh*8;
    unsigned dB = sbase + (bhalf ? BLO_OFF : BHI_OFF) + bo*48 + bh*16;
    unsigned loff = (lane & 15)*48 + (lane >> 4)*16;
    float c[2][4][4] = {};
    CPA(dAhi, g_basesHI + (size_t)(x0+row)*MODE + ch*8);
    CPA(dAlo, g_basesLO + (size_t)(x0+row)*MODE + ch*8);
    CPA(dB, sBy);
    CPC();
    for (int chn = 0; chn < nch; chn++){
        int cur = chn & 1, nxt = cur ^ 1;
        if (chn + 1 < nch){
            int cn = chn + 1;
            if (cn < 8){
                CPA(dAhi + nxt*ABUF, g_basesHI + (size_t)(x0+row)*MODE + cn*16 + ch*8);
                CPA(dAlo + nxt*ABUF, g_basesLO + (size_t)(x0+row)*MODE + cn*16 + ch*8);
                CPA(dB + nxt*BBUF, sBy + cn*16);
            } else {
                CPA(dAhi + nxt*ABUF, hxHI + ((size_t)b*NXS + x0 + row)*DIMC + (cn-8)*16 + ch*8);
                CPA(dAlo + nxt*ABUF, hxLO + ((size_t)b*NXS + x0 + row)*DIMC + (cn-8)*16 + ch*8);
                CPA(dB + nxt*BBUF, sBw + (cn-8)*16);
            }
            CPC(); CPW1();
        } else CPW0();
        __syncthreads();
        unsigned offA = cur*ABUF + loff;
        unsigned offB = cur*BBUF + loff;
        unsigned Ah[2][4], Al[2][4], Bh[2][4], Bl[2][4];
        #pragma unroll
        for (int tm = 0; tm < 2; tm++){
            LDSM4(Ah[tm], bAhi + offA + (wmA*32 + tm*16)*48);
            LDSM4(Al[tm], bAlo + offA + (wmA*32 + tm*16)*48);
        }
        #pragma unroll
        for (int p = 0; p < 2; p++){
            LDSM4(Bh[p], bBhi + offB + (wnA*32 + p*16)*48);
            LDSM4(Bl[p], bBlo + offB + (wnA*32 + p*16)*48);
        }
        #pragma unroll
        for (int tm = 0; tm < 2; tm++)
            #pragma unroll
            for (int tn = 0; tn < 4; tn++){
                int p = tn >> 1, e = tn & 1;
                unsigned bhv[2] = {Bh[p][e], Bh[p][e+2]};
                unsigned blv[2] = {Bl[p][e], Bl[p][e+2]};
                MMA(c[tm][tn], Ah[tm], bhv);
                MMA(c[tm][tn], Al[tm], bhv);
                MMA(c[tm][tn], Ah[tm], blv);
            }
        __syncthreads();
    }
    #pragma unroll
    for (int tm = 0; tm < 2; tm++)
        #pragma unroll
        for (int tn = 0; tn < 4; tn++){
            int xr = wmA*32 + tm*16 + g;
            int oc = wnA*32 + tn*8 + t*2;
            Csm[oc][xr]     = c[tm][tn][0]; Csm[oc+1][xr]   = c[tm][tn][1];
            Csm[oc][xr+8]   = c[tm][tn][2]; Csm[oc+1][xr+8] = c[tm][tn][3];
        }
    __syncthreads();
    {
        int o = tid >> 2;
        float bias = tail3 ? g_bias0[o] : biasv[o];
        float w0 = 0.f, w1 = 0.f, w2c = 0.f;
        if (tail3){ w0 = g_Wc0T[o]; w1 = g_Wc0T[64+o]; w2c = g_Wc0T[128+o]; }
        #pragma unroll 4
        for (int j = 0; j < 32; j++){
            int xr = (tid & 3)*32 + j;
            float v = Csm[o][xr] + bias;
            if (tail3){
                int gx = x0 + xr;
                v += g_xT[((size_t)b*IN_DIM + 0)*NXS + gx]*w0
                   + g_xT[((size_t)b*IN_DIM + 1)*NXS + gx]*w1
                   + g_xT[((size_t)b*IN_DIM + 2)*NXS + gx]*w2c;
            }
            if (!is_last) CsmU[o][xr] = pk_split(gelu_f(v));
            else          Csm[o][xr] = v;
        }
    }
    __syncthreads();
    if (!is_last){
        for (int i = tid; i < 128*32; i += 256){
            int xx = i >> 5, cp = i & 31;
            unsigned u0 = CsmU[2*cp][xx], u1 = CsmU[2*cp+1][xx];
            unsigned hi = (u0 >> 16) | (u1 & 0xFFFF0000u);
            unsigned lo = (u0 & 0xFFFFu) | (u1 << 16);
            size_t base = ((size_t)b*NXS + x0 + xx)*DIMC;
            ((unsigned*)(hxoHI + base))[cp] = hi;
            ((unsigned*)(hxoLO + base))[cp] = lo;
        }
        return;
    }
    float c2[4][4][4] = {};
    int hh_ = tid & 1, xr_ = tid >> 1;
    for (int ks = 0; ks < 4; ks++){
        CPA(sbase + FBHI + row*48 + hh_*16, g_W1THI + row*64 + ks*16 + hh_*8);
        CPA(sbase + FBLO + row*48 + hh_*16, g_W1TLO + row*64 + ks*16 + hh_*8);
        CPC();
        {
            unsigned uh[4], ul[4];
            #pragma unroll
            for (int j = 0; j < 4; j++){
                ushortx h0,l0,h1,l1;
                split2(Csm[ks*16 + hh_*8 + 2*j][xr_], h0, l0);
                split2(Csm[ks*16 + hh_*8 + 2*j+1][xr_], h1, l1);
                uh[j] = (unsigned)h0 | ((unsigned)h1 << 16);
                ul[j] = (unsigned)l0 | ((unsigned)l1 << 16);
            }
            *(uint4*)(pool + FAHI + xr_*48 + hh_*16) = make_uint4(uh[0],uh[1],uh[2],uh[3]);
            *(uint4*)(pool + FALO + xr_*48 + hh_*16) = make_uint4(ul[0],ul[1],ul[2],ul[3]);
        }
        CPW0();
        __syncthreads();
        unsigned Ah[4][4], Al[4][4], Bh[2][4], Bl[2][4];
        #pragma unroll
        for (int tm = 0; tm < 4; tm++){
            LDSM4(Ah[tm], sbase + FAHI + loff + (wm*64 + tm*16)*48);
            LDSM4(Al[tm], sbase + FALO + loff + (wm*64 + tm*16)*48);
        }
        #pragma unroll
        for (int p = 0; p < 2; p++){
            LDSM4(Bh[p], sbase + FBHI + loff + (wn*32 + p*16)*48);
            LDSM4(Bl[p], sbase + FBLO + loff + (wn*32 + p*16)*48);
        }
        #pragma unroll
        for (int tm = 0; tm < 4; tm++)
            #pragma unroll
            for (int tn = 0; tn < 4; tn++){
                int p = tn >> 1, e = tn & 1;
                unsigned bh[2] = {Bh[p][e], Bh[p][e+2]};
                unsigned bl[2] = {Bl[p][e], Bl[p][e+2]};
                MMA(c2[tm][tn], Ah[tm], bh);
                MMA(c2[tm][tn], Al[tm], bh);
                MMA(c2[tm][tn], Ah[tm], bl);
            }
        __syncthreads();
    }
    float part[4][2] = {};
    #pragma unroll
    for (int tn = 0; tn < 4; tn++){
        int f0 = wn*32 + tn*8 + t*2;
        float b10 = b1[f0], b11 = b1[f0+1];
        float w20 = W2[f0], w21 = W2[f0+1];
        #pragma unroll
        for (int tm = 0; tm < 4; tm++){
            part[tm][0] += gelu_f(c2[tm][tn][0]+b10)*w20 + gelu_f(c2[tm][tn][1]+b11)*w21;
            part[tm][1] += gelu_f(c2[tm][tn][2]+b10)*w20 + gelu_f(c2[tm][tn][3]+b11)*w21;
        }
    }
    float (*red)[16] = (float(*)[16])(pool + FAHI);
    #pragma unroll
    for (int tm = 0; tm < 4; tm++){
        int xr0 = wm*64 + tm*16 + g;
        red[xr0][wn*4 + t]   = part[tm][0];
        red[xr0+8][wn*4 + t] = part[tm][1];
    }
    __syncthreads();
    if (tid < 128){
        float s = b2[0];
        #pragma unroll
        for (int k = 0; k < 16; k++) s += red[tid][k];
        out[(size_t)b*NXS + x0 + tid] = s;
    }
}

// ---------------------------------------------------------------------------
extern "C" void kernel_launch(void* const* d_in, const int* in_sizes, int n_in,
                              void* d_out, int out_size){
    (void)in_sizes; (void)n_in; (void)out_size;
    const float* x      = (const float*)d_in[0];
    const float* bases  = (const float*)d_in[1];
    const float* wbases = (const float*)d_in[2];
    const float* product= (const float*)d_in[3];
    const float* Do     = (const float*)d_in[4];
    const float* Di     = (const float*)d_in[5];
    const float* A      = (const float*)d_in[6];
    const float* Bm     = (const float*)d_in[7];
    const float* W_sp   = (const float*)d_in[8];
    const float* W_conv = (const float*)d_in[9];
    const float* b_conv = (const float*)d_in[10];
    const float* W0     = (const float*)d_in[11];
    const float* b0     = (const float*)d_in[12];
    const float* W1     = (const float*)d_in[13];
    const float* b1     = (const float*)d_in[14];
    const float* W2     = (const float*)d_in[15];
    const float* b2     = (const float*)d_in[16];
    float* out = (float*)d_out;

    cudaFuncSetAttribute(k_L_mma, cudaFuncAttributeMaxDynamicSharedMemorySize, LSM_LAST);

    ushortx *hxHa,*hxLa,*hxHb,*hxLb;
    cudaGetSymbolAddress((void**)&hxHa, g_hxHIa);
    cudaGetSymbolAddress((void**)&hxLa, g_hxLOa);
    cudaGetSymbolAddress((void**)&hxHb, g_hxHIb);
    cudaGetSymbolAddress((void**)&hxLb, g_hxLOb);

    k_basesP<<<(NXS*MODE)/256, 256>>>(bases);
    k_wbTP<<<dim3(NXS/32, MODE/32), dim3(32,8)>>>(wbases);
    k_W1TP<<<(FCD*DIMC)/256, 256>>>(W1);
    k_buildH<<<dim3(NJ, MODE), MODE>>>(Do, Di, product, A, Bm);
    k_xT<<<(BSZ*NXS*IN_DIM)/256, 256>>>(x);
    k_prep0<<<1, DIMC>>>(W_conv, W0, b0, b_conv);

    // ---- layer 0 ----
    k_T<<<dim3(BSZ, T_SPLITS), MODE>>>(wbases);
    k_xh0<<<BSZ, 256>>>(W0, b0);
    k_xh1_mma<<<dim3(BSZ, NJ), 256>>>();
    k_WrT<<<(DIMC*DIMC*NJ)/256, 256>>>(W_sp, 0);
    k_y_mma<<<dim3(BSZ, Y_SPLITS), 256>>>();
    k_reduce_y<<<(BSZ*DIMC*MODE)/256, 256>>>();
    k_L_mma<<<dim3(BSZ, NXS/128), 256, LSM_MID>>>(hxHa, hxLa, hxHa, hxLa,
                                                  nullptr,
                                                  b1, W2, b2, out, 1, 0);
    // ---- layers 1,2 ----
    const ushortx *hxH = hxHa, *hxL = hxLa;
    ushortx *hxHo = hxHb, *hxLo = hxLb;
    for (int li = 1; li < N_LAYERS; li++){
        int last = (li == N_LAYERS-1) ? 1 : 0;
        k_xh_mma<<<dim3((BSZ*DIMC)/128, XH_SPLITS), 256>>>(hxH, hxL);
        k_reduce_xh<<<(BSZ*DIMC*MODE)/256, 256>>>();
        k_xh1_mma<<<dim3(BSZ, NJ), 256>>>();
        k_WrT<<<(DIMC*DIMC*NJ)/256, 256>>>(W_sp, li);
        k_y_mma<<<dim3(BSZ, Y_SPLITS), 256>>>();
        k_reduce_y<<<(BSZ*DIMC*MODE)/256, 256>>>();
        k_WcP<<<(DIMC*DIMC)/256, 256>>>(W_conv, li);
        k_L_mma<<<dim3(BSZ, NXS/128), 256, last ? LSM_LAST : LSM_MID>>>(
                                             hxH, hxL, hxHo, hxLo,
                                             &b_conv[(size_t)li*DIMC],
                                             b1, W2, b2, out, 0, last);
        const ushortx* t3 = hxH; hxH = hxHo; hxHo = (ushortx*)t3;
        const ushortx* t4 = hxL; hxL = hxLo; hxLo = (ushortx*)t4;
    }
}

// round 16
// speedup vs baseline: 1.0929x; 1.0098x over previous
#include <cuda_runtime.h>
#include <cuda_bf16.h>
#include <math.h>
#include <stdint.h>

#define BSZ 32
#define NXS 16384
#define IN_DIM 3
#define DIMC 64
#define NJ 16
#define MODE 128
#define RANKR 4
#define FCD 128
#define N_LAYERS 3
#define XH_SPLITS 8
#define Y_SPLITS 4
#define T_SPLITS 8

typedef unsigned short ushortx;

__device__ ushortx g_hxHIa[(size_t)BSZ*NXS*DIMC];
__device__ ushortx g_hxLOa[(size_t)BSZ*NXS*DIMC];
__device__ ushortx g_hxHIb[(size_t)BSZ*NXS*DIMC];
__device__ ushortx g_hxLOb[(size_t)BSZ*NXS*DIMC];
__device__ ushortx g_wbTHI[(size_t)MODE*NXS];
__device__ ushortx g_wbTLO[(size_t)MODE*NXS];
__device__ ushortx g_basesHI[(size_t)NXS*MODE];
__device__ ushortx g_basesLO[(size_t)NXS*MODE];
__device__ ushortx g_W1THI[FCD*DIMC];
__device__ ushortx g_W1TLO[FCD*DIMC];
__device__ ushortx g_HjHI[NJ*MODE*MODE];
__device__ ushortx g_HjLO[NJ*MODE*MODE];
__device__ ushortx g_xhHI[BSZ*DIMC*MODE];
__device__ ushortx g_xhLO[BSZ*DIMC*MODE];
__device__ ushortx g_x1THI[(size_t)BSZ*MODE*(DIMC*NJ)];
__device__ ushortx g_x1TLO[(size_t)BSZ*MODE*(DIMC*NJ)];
__device__ ushortx g_WrTTHI[DIMC*DIMC*NJ];
__device__ ushortx g_WrTTLO[DIMC*DIMC*NJ];
__device__ ushortx g_yHI[BSZ*DIMC*MODE];
__device__ ushortx g_yLO[BSZ*DIMC*MODE];
__device__ ushortx g_WcHI[DIMC*DIMC];
__device__ ushortx g_WcLO[DIMC*DIMC];
__device__ float g_xT[BSZ*IN_DIM*NXS];
__device__ float g_xhp[XH_SPLITS*BSZ*DIMC*MODE];
__device__ float g_yp [Y_SPLITS*BSZ*DIMC*MODE];
__device__ float g_Tp [T_SPLITS*BSZ*4*MODE];
__device__ float g_Wc0T[IN_DIM*DIMC];
__device__ float g_bias0[DIMC];

__device__ __forceinline__ float gelu_f(float v){
    return 0.5f * v * (1.0f + erff(v * 0.70710678118654752440f));
}
__device__ __forceinline__ void split2(float x, ushortx& hi, ushortx& lo){
    __nv_bfloat16 h = __float2bfloat16(x);
    hi = __bfloat16_as_ushort(h);
    lo = __bfloat16_as_ushort(__float2bfloat16(x - __bfloat162float(h)));
}
__device__ __forceinline__ unsigned pk_split(float x){
    ushortx hi, lo; split2(x, hi, lo);
    return ((unsigned)hi << 16) | (unsigned)lo;
}
#define MMA(c,a,b) asm volatile( \
    "mma.sync.aligned.m16n8k16.row.col.f32.bf16.bf16.f32 " \
    "{%0,%1,%2,%3}, {%4,%5,%6,%7}, {%8,%9}, {%0,%1,%2,%3};" \
    : "+f"((c)[0]), "+f"((c)[1]), "+f"((c)[2]), "+f"((c)[3]) \
    : "r"((a)[0]), "r"((a)[1]), "r"((a)[2]), "r"((a)[3]), "r"((b)[0]), "r"((b)[1]))
#define LDSM4(f,addr) asm volatile( \
    "ldmatrix.sync.aligned.m8n8.x4.shared.b16 {%0,%1,%2,%3}, [%4];" \
    : "=r"((f)[0]), "=r"((f)[1]), "=r"((f)[2]), "=r"((f)[3]) : "r"(addr))
#define LDSM4T(f,addr) asm volatile( \
    "ldmatrix.sync.aligned.m8n8.x4.trans.shared.b16 {%0,%1,%2,%3}, [%4];" \
    : "=r"((f)[0]), "=r"((f)[1]), "=r"((f)[2]), "=r"((f)[3]) : "r"(addr))
#define CPA(dst,src) asm volatile("cp.async.cg.shared.global [%0], [%1], 16;" :: "r"(dst), "l"(src))
#define CPC() asm volatile("cp.async.commit_group;" ::: "memory")
#define CPW1() asm volatile("cp.async.wait_group 1;" ::: "memory")
#define CPW0() asm volatile("cp.async.wait_group 0;" ::: "memory")

// ============ fused prep: basesP | W1TP | buildH | xT | prep0 ============
#define PB_BASES 8192
#define PB_W1    (PB_BASES + 32)
#define PB_H     (PB_W1 + 1024)
#define PB_XT    (PB_H + 6144)
#define PB_TOTAL (PB_XT + 1)
__global__ void k_prep_all(const float* __restrict__ bases, const float* __restrict__ W1,
                           const float* __restrict__ Do, const float* __restrict__ Di,
                           const float* __restrict__ pr, const float* __restrict__ A,
                           const float* __restrict__ Bm, const float* __restrict__ x,
                           const float* __restrict__ W_conv, const float* __restrict__ W0,
                           const float* __restrict__ b0, const float* __restrict__ b_conv){
    int gb = blockIdx.x, tid = threadIdx.x;
    if (gb < PB_BASES){
        int i = gb*256 + tid;
        split2(bases[i], g_basesHI[i], g_basesLO[i]);
    } else if (gb < PB_W1){
        int i = (gb - PB_BASES)*256 + tid;          // < 8192
        int f = i >> 6, c = i & 63;
        split2(W1[c*FCD + f], g_W1THI[i], g_W1TLO[i]);
    } else if (gb < PB_H){
        int i = (gb - PB_W1)*256 + tid;             // < 262144
        int j = i >> 14, r = i & 16383;
        int k = r >> 7, l = r & 127;
        float s = Do[j*MODE + k] * Di[j*MODE + l] * pr[k*MODE + l];
        #pragma unroll
        for (int rr = 0; rr < RANKR; rr++)
            s += A[(j*RANKR + rr)*MODE + k] * Bm[(j*RANKR + rr)*MODE + l];
        split2(s, g_HjHI[i], g_HjLO[i]);
    } else if (gb < PB_XT){
        int i = (gb - PB_H)*256 + tid;              // < 1572864
        int d = i % 3, t = i / 3;
        g_xT[((size_t)(t >> 14)*IN_DIM + d)*NXS + (t & (NXS-1))] = x[i];
    } else {
        if (tid >= DIMC) return;
        int o = tid;
        float w0s = 0.f, w1s = 0.f, w2s = 0.f, bb = b_conv[o];
        for (int c = 0; c < DIMC; c++){
            float wc = W_conv[o*DIMC + c];
            w0s += wc*W0[c]; w1s += wc*W0[DIMC+c]; w2s += wc*W0[2*DIMC+c];
            bb  += wc*b0[c];
        }
        g_Wc0T[o] = w0s; g_Wc0T[64+o] = w1s; g_Wc0T[128+o] = w2s; g_bias0[o] = bb;
    }
}
__global__ void k_wbTP(const float* __restrict__ wb){
    __shared__ float t[32][33];
    int x0 = blockIdx.x * 32, k0 = blockIdx.y * 32;
    for (int i = threadIdx.y; i < 32; i += 8)
        t[i][threadIdx.x] = wb[(size_t)(x0 + i)*MODE + k0 + threadIdx.x];
    __syncthreads();
    for (int i = threadIdx.y; i < 32; i += 8){
        size_t o = (size_t)(k0 + i)*NXS + x0 + threadIdx.x;
        split2(t[threadIdx.x][i], g_wbTHI[o], g_wbTLO[o]);
    }
}
__global__ void k_T(const float* __restrict__ wbases){
    int b = blockIdx.x, s = blockIdx.y;
    int x0 = s * (NXS / T_SPLITS);
    int k = threadIdx.x;
    __shared__ float xs[3][128];
    float a0=0.f, a1=0.f, a2=0.f, a3=0.f;
    for (int xt = 0; xt < (NXS/T_SPLITS)/128; xt++){
        __syncthreads();
        xs[0][k] = g_xT[((size_t)b*IN_DIM + 0)*NXS + x0 + xt*128 + k];
        xs[1][k] = g_xT[((size_t)b*IN_DIM + 1)*NXS + x0 + xt*128 + k];
        xs[2][k] = g_xT[((size_t)b*IN_DIM + 2)*NXS + x0 + xt*128 + k];
        __syncthreads();
        #pragma unroll 8
        for (int xi = 0; xi < 128; xi++){
            float w = wbases[(size_t)(x0 + xt*128 + xi)*MODE + k];
            a0 += xs[0][xi]*w; a1 += xs[1][xi]*w; a2 += xs[2][xi]*w; a3 += w;
        }
    }
    size_t base = (((size_t)s*BSZ + b)*4)*MODE + k;
    g_Tp[base] = a0; g_Tp[base+MODE] = a1; g_Tp[base+2*MODE] = a2; g_Tp[base+3*MODE] = a3;
}
__global__ void k_xh0(const float* __restrict__ W0, const float* __restrict__ b0){
    int b = blockIdx.x;
    __shared__ float Ts[4][128];
    int tid = threadIdx.x;
    for (int e = tid; e < 4*MODE; e += 256){
        int d = e >> 7, k = e & 127;
        float s = 0.f;
        #pragma unroll
        for (int s8 = 0; s8 < T_SPLITS; s8++)
            s += g_Tp[(((size_t)s8*BSZ + b)*4 + d)*MODE + k];
        Ts[d][k] = s;
    }
    __syncthreads();
    for (int o = tid; o < DIMC*MODE; o += 256){
        int c = o >> 7, k = o & 127;
        float v = W0[c]*Ts[0][k] + W0[DIMC+c]*Ts[1][k] + W0[2*DIMC+c]*Ts[2][k] + b0[c]*Ts[3][k];
        size_t idx = (size_t)b*DIMC*MODE + o;
        split2(v, g_xhHI[idx], g_xhLO[idx]);
    }
}

// ===== GEMM1 (R12 pipeline: CPW1) =====
__global__ void __launch_bounds__(256) k_xh_mma(const ushortx* __restrict__ hxHI,
                                                const ushortx* __restrict__ hxLO){
    __shared__ __align__(16) unsigned smA[2][2][16][68];
    __shared__ __align__(16) unsigned smB[2][2][128][12];
    const int NIT = (NXS/XH_SPLITS)/16;
    int tid = threadIdx.x, lane = tid & 31, wid = tid >> 5;
    int wm = wid >> 2, wn = wid & 3, g = lane >> 2, t = lane & 3;
    int m0 = blockIdx.x * 128, b0 = blockIdx.x * 2;
    int k0 = blockIdx.y * (NXS / XH_SPLITS);
    int xr = tid >> 4, bl = (tid >> 3) & 1, cq = tid & 7;
    const ushortx* sAh = hxHI + ((size_t)(b0+bl)*NXS + k0 + xr)*DIMC + cq*8;
    const ushortx* sAl = hxLO + ((size_t)(b0+bl)*NXS + k0 + xr)*DIMC + cq*8;
    unsigned dAh = (unsigned)__cvta_generic_to_shared(&smA[0][0][xr][bl*32 + cq*4]);
    unsigned dAl = (unsigned)__cvta_generic_to_shared(&smA[1][0][xr][bl*32 + cq*4]);
    int rB = tid >> 1, chB = tid & 1;
    const ushortx* sBh = g_wbTHI + (size_t)rB*NXS + k0 + chB*8;
    const ushortx* sBl = g_wbTLO + (size_t)rB*NXS + k0 + chB*8;
    unsigned dBh = (unsigned)__cvta_generic_to_shared(&smB[0][0][rB][chB*4]);
    unsigned dBl = (unsigned)__cvta_generic_to_shared(&smB[1][0][rB][chB*4]);
    unsigned bAh = (unsigned)__cvta_generic_to_shared(&smA[0][0][0][0]);
    unsigned bAl = (unsigned)__cvta_generic_to_shared(&smA[1][0][0][0]);
    unsigned bBh = (unsigned)__cvta_generic_to_shared(&smB[0][0][0][0]);
    unsigned bBl = (unsigned)__cvta_generic_to_shared(&smB[1][0][0][0]);
    const unsigned ABUFO = 16*68*4, BBUFO = 128*48;
    unsigned loffT = ((lane & 7) + (lane >> 4)*8)*272 + ((lane >> 3) & 1)*16;
    unsigned loff  = (lane & 15)*48 + (lane >> 4)*16;
    float c[4][4][4] = {};
    CPA(dAh, sAh); CPA(dAl, sAl); CPA(dBh, sBh); CPA(dBl, sBl);
    CPC();
    for (int it = 0; it < NIT; it++){
        int cur = it & 1, nxt = cur ^ 1;
        if (it + 1 < NIT){
            CPA(dAh + nxt*ABUFO, sAh + (size_t)(it+1)*16*DIMC);
            CPA(dAl + nxt*ABUFO, sAl + (size_t)(it+1)*16*DIMC);
            CPA(dBh + nxt*BBUFO, sBh + (it+1)*16);
            CPA(dBl + nxt*BBUFO, sBl + (it+1)*16);
            CPC(); CPW1();
        } else CPW0();
        __syncthreads();
        unsigned Ah[4][4], Al[4][4], Bh[2][4], Bl[2][4];
        #pragma unroll
        for (int tm = 0; tm < 4; tm++){
            LDSM4T(Ah[tm], bAh + cur*ABUFO + loffT + (wm*64 + tm*16)*2);
            LDSM4T(Al[tm], bAl + cur*ABUFO + loffT + (wm*64 + tm*16)*2);
        }
        #pragma unroll
        for (int p = 0; p < 2; p++){
            LDSM4(Bh[p], bBh + cur*BBUFO + loff + (wn*32 + p*16)*48);
            LDSM4(Bl[p], bBl + cur*BBUFO + loff + (wn*32 + p*16)*48);
        }
        #pragma unroll
        for (int tm = 0; tm < 4; tm++)
            #pragma unroll
            for (int tn = 0; tn < 4; tn++){
                int p = tn >> 1, e = tn & 1;
                unsigned bh[2] = {Bh[p][e], Bh[p][e+2]};
                unsigned bl[2] = {Bl[p][e], Bl[p][e+2]};
                MMA(c[tm][tn], Ah[tm], bh);
                MMA(c[tm][tn], Al[tm], bh);
                MMA(c[tm][tn], Ah[tm], bl);
            }
        __syncthreads();
    }
    float* dst = &g_xhp[(size_t)blockIdx.y*(BSZ*DIMC*MODE)];
    #pragma unroll
    for (int tm = 0; tm < 4; tm++)
        #pragma unroll
        for (int tn = 0; tn < 4; tn++){
            int m = m0 + wm*64 + tm*16 + g;
            int n = wn*32 + tn*8 + t*2;
            *(float2*)&dst[(size_t)m*MODE + n]     = make_float2(c[tm][tn][0], c[tm][tn][1]);
            *(float2*)&dst[(size_t)(m+8)*MODE + n] = make_float2(c[tm][tn][2], c[tm][tn][3]);
        }
}
__global__ void k_reduce_xh(){
    int i = blockIdx.x * 256 + threadIdx.x;
    float s = 0.f;
    #pragma unroll
    for (int k = 0; k < XH_SPLITS; k++) s += g_xhp[(size_t)k*(BSZ*DIMC*MODE) + i];
    split2(s, g_xhHI[i], g_xhLO[i]);
}

// ===== xh1 (mma, R12 pipeline) =====
__global__ void __launch_bounds__(256) k_xh1_mma(){
    __shared__ __align__(16) unsigned smA[2][2][64][12];
    __shared__ __align__(16) unsigned smB[2][2][128][12];
    int tid = threadIdx.x, lane = tid & 31, wid = tid >> 5;
    int wm = wid >> 2, wn = wid & 3, g = lane >> 2, t = lane & 3;
    int b = blockIdx.x, j = blockIdx.y;
    unsigned loff = (lane & 15)*48 + (lane >> 4)*16;
    int aA = tid >> 7, rA = (tid >> 1) & 63, hA = tid & 1;
    const ushortx* srcA = (aA ? g_xhLO : g_xhHI) + ((size_t)b*DIMC + rA)*MODE + hA*8;
    unsigned dA = (unsigned)__cvta_generic_to_shared(&smA[aA][0][rA][hA*4]);
    unsigned bAh = (unsigned)__cvta_generic_to_shared(&smA[0][0][0][0]);
    unsigned bAl = (unsigned)__cvta_generic_to_shared(&smA[1][0][0][0]);
    unsigned bBh = (unsigned)__cvta_generic_to_shared(&smB[0][0][0][0]);
    unsigned bBl = (unsigned)__cvta_generic_to_shared(&smB[1][0][0][0]);
    const unsigned ABUFO = 64*12*4, BBUFO = 128*12*4;
    float c[2][4][4] = {};
    CPA(dA, srcA);
    #pragma unroll
    for (int rep = 0; rep < 2; rep++){
        int cid = tid + rep*256;
        int aB = cid >> 8, rBx = (cid >> 1) & 127, hB = cid & 1;
        const ushortx* srcB = (aB ? g_HjLO : g_HjHI) + ((size_t)j*MODE + rBx)*MODE + hB*8;
        CPA((unsigned)__cvta_generic_to_shared(&smB[aB][0][rBx][hB*4]), srcB);
    }
    CPC();
    for (int ks = 0; ks < 8; ks++){
        int cur = ks & 1, nxt = cur ^ 1;
        if (ks + 1 < 8){
            CPA(dA + nxt*ABUFO, srcA + (ks+1)*16);
            #pragma unroll
            for (int rep = 0; rep < 2; rep++){
                int cid = tid + rep*256;
                int aB = cid >> 8, rBx = (cid >> 1) & 127, hB = cid & 1;
                const ushortx* srcB = (aB ? g_HjLO : g_HjHI) + ((size_t)j*MODE + rBx)*MODE + hB*8;
                CPA((unsigned)__cvta_generic_to_shared(&smB[aB][0][rBx][hB*4]) + nxt*BBUFO,
                    srcB + (ks+1)*16);
            }
            CPC(); CPW1();
        } else CPW0();
        __syncthreads();
        unsigned offA = cur*ABUFO + loff, offB = cur*BBUFO + loff;
        unsigned Ah[2][4], Al[2][4], Bh[2][4], Bl[2][4];
        #pragma unroll
        for (int tm = 0; tm < 2; tm++){
            LDSM4(Ah[tm], bAh + offA + (wm*32 + tm*16)*48);
            LDSM4(Al[tm], bAl + offA + (wm*32 + tm*16)*48);
        }
        #pragma unroll
        for (int p = 0; p < 2; p++){
            LDSM4(Bh[p], bBh + offB + (wn*32 + p*16)*48);
            LDSM4(Bl[p], bBl + offB + (wn*32 + p*16)*48);
        }
        #pragma unroll
        for (int tm = 0; tm < 2; tm++)
            #pragma unroll
            for (int tn = 0; tn < 4; tn++){
                int p = tn >> 1, e = tn & 1;
                unsigned bh[2] = {Bh[p][e], Bh[p][e+2]};
                unsigned bl[2] = {Bl[p][e], Bl[p][e+2]};
                MMA(c[tm][tn], Ah[tm], bh);
                MMA(c[tm][tn], Al[tm], bh);
                MMA(c[tm][tn], Ah[tm], bl);
            }
        __syncthreads();
    }
    #pragma unroll
    for (int tm = 0; tm < 2; tm++)
        #pragma unroll
        for (int tn = 0; tn < 4; tn++){
            int m = wm*32 + tm*16 + g;
            int n = wn*32 + tn*8 + t*2;
            #pragma unroll
            for (int e = 0; e < 4; e++){
                int mm = m + (e >> 1)*8, nn = n + (e & 1);
                size_t o = ((size_t)b*MODE + nn)*(DIMC*NJ) + j*64 + mm;
                split2(c[tm][tn][e], g_x1THI[o], g_x1TLO[o]);
            }
        }
}
// WrT (blocks 0..255) + WcP (blocks 256..271, when do_wc)
__global__ void k_WrTWc(const float* __restrict__ W_sp, const float* __restrict__ W_conv,
                        int li, int do_wc){
    int gb = blockIdx.x;
    if (gb < 256){
        int idx = gb * 256 + threadIdx.x;
        int p = idx & 1023, o = idx >> 10;
        int j = p >> 6, cc = p & 63;
        float v = W_sp[(((size_t)li*DIMC + cc)*DIMC + o)*NJ + j];
        split2(v, g_WrTTHI[idx], g_WrTTLO[idx]);
    } else if (do_wc){
        int i = (gb - 256) * 256 + threadIdx.x;   // < 4096
        split2(W_conv[(size_t)li*DIMC*DIMC + i], g_WcHI[i], g_WcLO[i]);
    }
}
__global__ void __launch_bounds__(256) k_y_mma(){
    __shared__ __align__(16) unsigned smA[2][2][64][12];
    __shared__ __align__(16) unsigned smB[2][2][128][12];
    int tid = threadIdx.x, lane = tid & 31, wid = tid >> 5;
    int wm = wid >> 2, wn = wid & 3, g = lane >> 2, t = lane & 3;
    int b = blockIdx.x, sp = blockIdx.y;
    int p0 = sp * 256;
    unsigned loff = (lane & 15)*48 + (lane >> 4)*16;
    int aA = tid >> 7, rA = (tid >> 1) & 63, hA = tid & 1;
    const ushortx* srcA = (aA ? g_WrTTLO : g_WrTTHI) + (size_t)rA*(DIMC*NJ) + p0 + hA*8;
    unsigned dA = (unsigned)__cvta_generic_to_shared(&smA[aA][0][rA][hA*4]);
    unsigned bAh = (unsigned)__cvta_generic_to_shared(&smA[0][0][0][0]);
    unsigned bAl = (unsigned)__cvta_generic_to_shared(&smA[1][0][0][0]);
    unsigned bBh = (unsigned)__cvta_generic_to_shared(&smB[0][0][0][0]);
    unsigned bBl = (unsigned)__cvta_generic_to_shared(&smB[1][0][0][0]);
    const unsigned ABUFO = 64*12*4, BBUFO = 128*12*4;
    float c[2][4][4] = {};
    CPA(dA, srcA);
    #pragma unroll
    for (int rep = 0; rep < 2; rep++){
        int cid = tid + rep*256;
        int aB = cid >> 8, rBx = (cid >> 1) & 127, hB = cid & 1;
        const ushortx* srcB = (aB ? g_x1TLO : g_x1THI) + ((size_t)b*MODE + rBx)*(DIMC*NJ) + p0 + hB*8;
        CPA((unsigned)__cvta_generic_to_shared(&smB[aB][0][rBx][hB*4]), srcB);
    }
    CPC();
    for (int ks = 0; ks < 16; ks++){
        int cur = ks & 1, nxt = cur ^ 1;
        if (ks + 1 < 16){
            CPA(dA + nxt*ABUFO, srcA + (ks+1)*16);
            #pragma unroll
            for (int rep = 0; rep < 2; rep++){
                int cid = tid + rep*256;
                int aB = cid >> 8, rBx = (cid >> 1) & 127, hB = cid & 1;
                const ushortx* srcB = (aB ? g_x1TLO : g_x1THI) + ((size_t)b*MODE + rBx)*(DIMC*NJ) + p0 + hB*8;
                CPA((unsigned)__cvta_generic_to_shared(&smB[aB][0][rBx][hB*4]) + nxt*BBUFO,
                    srcB + (ks+1)*16);
            }
            CPC(); CPW1();
        } else CPW0();
        __syncthreads();
        unsigned offA = cur*ABUFO + loff, offB = cur*BBUFO + loff;
        unsigned Ah[2][4], Al[2][4], Bh[2][4], Bl[2][4];
        #pragma unroll
        for (int tm = 0; tm < 2; tm++){
            LDSM4(Ah[tm], bAh + offA + (wm*32 + tm*16)*48);
            LDSM4(Al[tm], bAl + offA + (wm*32 + tm*16)*48);
        }
        #pragma unroll
        for (int p = 0; p < 2; p++){
            LDSM4(Bh[p], bBh + offB + (wn*32 + p*16)*48);
            LDSM4(Bl[p], bBl + offB + (wn*32 + p*16)*48);
        }
        #pragma unroll
        for (int tm = 0; tm < 2; tm++)
            #pragma unroll
            for (int tn = 0; tn < 4; tn++){
                int p = tn >> 1, e = tn & 1;
                unsigned bh[2] = {Bh[p][e], Bh[p][e+2]};
                unsigned bl[2] = {Bl[p][e], Bl[p][e+2]};
                MMA(c[tm][tn], Ah[tm], bh);
                MMA(c[tm][tn], Al[tm], bh);
                MMA(c[tm][tn], Ah[tm], bl);
            }
        __syncthreads();
    }
    float* dst = &g_yp[(size_t)sp*(BSZ*DIMC*MODE)];
    #pragma unroll
    for (int tm = 0; tm < 2; tm++)
        #pragma unroll
        for (int tn = 0; tn < 4; tn++){
            int m = wm*32 + tm*16 + g;
            int n = wn*32 + tn*8 + t*2;
            *(float2*)&dst[((size_t)b*DIMC + m)*MODE + n]     = make_float2(c[tm][tn][0], c[tm][tn][1]);
            *(float2*)&dst[((size_t)b*DIMC + m + 8)*MODE + n] = make_float2(c[tm][tn][2], c[tm][tn][3]);
        }
}
__global__ void k_reduce_y(){
    int i = blockIdx.x * 256 + threadIdx.x;
    float s = 0.f;
    #pragma unroll
    for (int k = 0; k < Y_SPLITS; k++) s += g_yp[(size_t)k*(BSZ*DIMC*MODE) + i];
    split2(s, g_yHI[i], g_yLO[i]);
}

// ===== GEMM2 + tensorized fc1 (unchanged from R15 best) =====
#define CSW 132
#define AHI_OFF 0
#define ALO_OFF 12288
#define BHI_OFF 24576
#define BLO_OFF 30720
#define ABUF 6144
#define BBUF 3072
#define FAHI 36864
#define FALO 43008
#define FBHI 49152
#define FBLO 55296
#define LSM_LAST 61440
#define LSM_MID  36864
__global__ void __launch_bounds__(256) k_L_mma(
    const ushortx* __restrict__ hxHI, const ushortx* __restrict__ hxLO,
    ushortx* __restrict__ hxoHI, ushortx* __restrict__ hxoLO,
    const float* __restrict__ biasv,
    const float* __restrict__ b1, const float* __restrict__ W2,
    const float* __restrict__ b2,
    float* __restrict__ out, int tail3, int is_last)
{
    extern __shared__ __align__(16) char pool[];
    float (*Csm)[CSW]  = (float(*)[CSW])pool;
    unsigned (*CsmU)[CSW] = (unsigned(*)[CSW])pool;
    int tid = threadIdx.x, lane = tid & 31, wid = tid >> 5;
    int wm = wid >> 2, wn = wid & 3, g = lane >> 2, t = lane & 3;
    int wmA = wid >> 1, wnA = wid & 1;
    int b = blockIdx.x;
    int x0 = blockIdx.y * 128;
    int row = tid >> 1, ch = tid & 1;
    int nch = tail3 ? 8 : 12;
    unsigned sbase = (unsigned)__cvta_generic_to_shared(pool);
    unsigned dAhi = sbase + AHI_OFF + row*48 + ch*16;
    unsigned dAlo = dAhi + (ALO_OFF - AHI_OFF);
    unsigned bAhi = sbase + AHI_OFF, bAlo = sbase + ALO_OFF;
    unsigned bBhi = sbase + BHI_OFF, bBlo = sbase + BLO_OFF;
    int bhalf = tid >> 7, bo = (tid >> 1) & 63, bh = tid & 1;
    const ushortx* sBy = (bhalf ? g_yLO : g_yHI) + ((size_t)b*DIMC + bo)*MODE + bh*8;
    const ushortx* sBw = (bhalf ? g_WcLO : g_WcHI) + (size_t)bo*DIMC + bh*8;
    unsigned dB = sbase + (bhalf ? BLO_OFF : BHI_OFF) + bo*48 + bh*16;
    unsigned loff = (lane & 15)*48 + (lane >> 4)*16;
    float c[2][4][4] = {};
    CPA(dAhi, g_basesHI + (size_t)(x0+row)*MODE + ch*8);
    CPA(dAlo, g_basesLO + (size_t)(x0+row)*MODE + ch*8);
    CPA(dB, sBy);
    CPC();
    for (int chn = 0; chn < nch; chn++){
        int cur = chn & 1, nxt = cur ^ 1;
        if (chn + 1 < nch){
            int cn = chn + 1;
            if (cn < 8){
                CPA(dAhi + nxt*ABUF, g_basesHI + (size_t)(x0+row)*MODE + cn*16 + ch*8);
                CPA(dAlo + nxt*ABUF, g_basesLO + (size_t)(x0+row)*MODE + cn*16 + ch*8);
                CPA(dB + nxt*BBUF, sBy + cn*16);
            } else {
                CPA(dAhi + nxt*ABUF, hxHI + ((size_t)b*NXS + x0 + row)*DIMC + (cn-8)*16 + ch*8);
                CPA(dAlo + nxt*ABUF, hxLO + ((size_t)b*NXS + x0 + row)*DIMC + (cn-8)*16 + ch*8);
                CPA(dB + nxt*BBUF, sBw + (cn-8)*16);
            }
            CPC(); CPW1();
        } else CPW0();
        __syncthreads();
        unsigned offA = cur*ABUF + loff;
        unsigned offB = cur*BBUF + loff;
        unsigned Ah[2][4], Al[2][4], Bh[2][4], Bl[2][4];
        #pragma unroll
        for (int tm = 0; tm < 2; tm++){
            LDSM4(Ah[tm], bAhi + offA + (wmA*32 + tm*16)*48);
            LDSM4(Al[tm], bAlo + offA + (wmA*32 + tm*16)*48);
        }
        #pragma unroll
        for (int p = 0; p < 2; p++){
            LDSM4(Bh[p], bBhi + offB + (wnA*32 + p*16)*48);
            LDSM4(Bl[p], bBlo + offB + (wnA*32 + p*16)*48);
        }
        #pragma unroll
        for (int tm = 0; tm < 2; tm++)
            #pragma unroll
            for (int tn = 0; tn < 4; tn++){
                int p = tn >> 1, e = tn & 1;
                unsigned bhv[2] = {Bh[p][e], Bh[p][e+2]};
                unsigned blv[2] = {Bl[p][e], Bl[p][e+2]};
                MMA(c[tm][tn], Ah[tm], bhv);
                MMA(c[tm][tn], Al[tm], bhv);
                MMA(c[tm][tn], Ah[tm], blv);
            }
        __syncthreads();
    }
    #pragma unroll
    for (int tm = 0; tm < 2; tm++)
        #pragma unroll
        for (int tn = 0; tn < 4; tn++){
            int xr = wmA*32 + tm*16 + g;
            int oc = wnA*32 + tn*8 + t*2;
            Csm[oc][xr]     = c[tm][tn][0]; Csm[oc+1][xr]   = c[tm][tn][1];
            Csm[oc][xr+8]   = c[tm][tn][2]; Csm[oc+1][xr+8] = c[tm][tn][3];
        }
    __syncthreads();
    {
        int o = tid >> 2;
        float bias = tail3 ? g_bias0[o] : biasv[o];
        float w0 = 0.f, w1 = 0.f, w2c = 0.f;
        if (tail3){ w0 = g_Wc0T[o]; w1 = g_Wc0T[64+o]; w2c = g_Wc0T[128+o]; }
        #pragma unroll 4
        for (int j = 0; j < 32; j++){
            int xr = (tid & 3)*32 + j;
            float v = Csm[o][xr] + bias;
            if (tail3){
                int gx = x0 + xr;
                v += g_xT[((size_t)b*IN_DIM + 0)*NXS + gx]*w0
                   + g_xT[((size_t)b*IN_DIM + 1)*NXS + gx]*w1
                   + g_xT[((size_t)b*IN_DIM + 2)*NXS + gx]*w2c;
            }
            if (!is_last) CsmU[o][xr] = pk_split(gelu_f(v));
            else          Csm[o][xr] = v;
        }
    }
    __syncthreads();
    if (!is_last){
        for (int i = tid; i < 128*32; i += 256){
            int xx = i >> 5, cp = i & 31;
            unsigned u0 = CsmU[2*cp][xx], u1 = CsmU[2*cp+1][xx];
            unsigned hi = (u0 >> 16) | (u1 & 0xFFFF0000u);
            unsigned lo = (u0 & 0xFFFFu) | (u1 << 16);
            size_t base = ((size_t)b*NXS + x0 + xx)*DIMC;
            ((unsigned*)(hxoHI + base))[cp] = hi;
            ((unsigned*)(hxoLO + base))[cp] = lo;
        }
        return;
    }
    float c2[4][4][4] = {};
    int hh_ = tid & 1, xr_ = tid >> 1;
    for (int ks = 0; ks < 4; ks++){
        CPA(sbase + FBHI + row*48 + hh_*16, g_W1THI + row*64 + ks*16 + hh_*8);
        CPA(sbase + FBLO + row*48 + hh_*16, g_W1TLO + row*64 + ks*16 + hh_*8);
        CPC();
        {
            unsigned uh[4], ul[4];
            #pragma unroll
            for (int j = 0; j < 4; j++){
                ushortx h0,l0,h1,l1;
                split2(Csm[ks*16 + hh_*8 + 2*j][xr_], h0, l0);
                split2(Csm[ks*16 + hh_*8 + 2*j+1][xr_], h1, l1);
                uh[j] = (unsigned)h0 | ((unsigned)h1 << 16);
                ul[j] = (unsigned)l0 | ((unsigned)l1 << 16);
            }
            *(uint4*)(pool + FAHI + xr_*48 + hh_*16) = make_uint4(uh[0],uh[1],uh[2],uh[3]);
            *(uint4*)(pool + FALO + xr_*48 + hh_*16) = make_uint4(ul[0],ul[1],ul[2],ul[3]);
        }
        CPW0();
        __syncthreads();
        unsigned Ah[4][4], Al[4][4], Bh[2][4], Bl[2][4];
        #pragma unroll
        for (int tm = 0; tm < 4; tm++){
            LDSM4(Ah[tm], sbase + FAHI + loff + (wm*64 + tm*16)*48);
            LDSM4(Al[tm], sbase + FALO + loff + (wm*64 + tm*16)*48);
        }
        #pragma unroll
        for (int p = 0; p < 2; p++){
            LDSM4(Bh[p], sbase + FBHI + loff + (wn*32 + p*16)*48);
            LDSM4(Bl[p], sbase + FBLO + loff + (wn*32 + p*16)*48);
        }
        #pragma unroll
        for (int tm = 0; tm < 4; tm++)
            #pragma unroll
            for (int tn = 0; tn < 4; tn++){
                int p = tn >> 1, e = tn & 1;
                unsigned bh[2] = {Bh[p][e], Bh[p][e+2]};
                unsigned bl[2] = {Bl[p][e], Bl[p][e+2]};
                MMA(c2[tm][tn], Ah[tm], bh);
                MMA(c2[tm][tn], Al[tm], bh);
                MMA(c2[tm][tn], Ah[tm], bl);
            }
        __syncthreads();
    }
    float part[4][2] = {};
    #pragma unroll
    for (int tn = 0; tn < 4; tn++){
        int f0 = wn*32 + tn*8 + t*2;
        float b10 = b1[f0], b11 = b1[f0+1];
        float w20 = W2[f0], w21 = W2[f0+1];
        #pragma unroll
        for (int tm = 0; tm < 4; tm++){
            part[tm][0] += gelu_f(c2[tm][tn][0]+b10)*w20 + gelu_f(c2[tm][tn][1]+b11)*w21;
            part[tm][1] += gelu_f(c2[tm][tn][2]+b10)*w20 + gelu_f(c2[tm][tn][3]+b11)*w21;
        }
    }
    float (*red)[16] = (float(*)[16])(pool + FAHI);
    #pragma unroll
    for (int tm = 0; tm < 4; tm++){
        int xr0 = wm*64 + tm*16 + g;
        red[xr0][wn*4 + t]   = part[tm][0];
        red[xr0+8][wn*4 + t] = part[tm][1];
    }
    __syncthreads();
    if (tid < 128){
        float s = b2[0];
        #pragma unroll
        for (int k = 0; k < 16; k++) s += red[tid][k];
        out[(size_t)b*NXS + x0 + tid] = s;
    }
}

// ---------------------------------------------------------------------------
extern "C" void kernel_launch(void* const* d_in, const int* in_sizes, int n_in,
                              void* d_out, int out_size){
    (void)in_sizes; (void)n_in; (void)out_size;
    const float* x      = (const float*)d_in[0];
    const float* bases  = (const float*)d_in[1];
    const float* wbases = (const float*)d_in[2];
    const float* product= (const float*)d_in[3];
    const float* Do     = (const float*)d_in[4];
    const float* Di     = (const float*)d_in[5];
    const float* A      = (const float*)d_in[6];
    const float* Bm     = (const float*)d_in[7];
    const float* W_sp   = (const float*)d_in[8];
    const float* W_conv = (const float*)d_in[9];
    const float* b_conv = (const float*)d_in[10];
    const float* W0     = (const float*)d_in[11];
    const float* b0     = (const float*)d_in[12];
    const float* W1     = (const float*)d_in[13];
    const float* b1     = (const float*)d_in[14];
    const float* W2     = (const float*)d_in[15];
    const float* b2     = (const float*)d_in[16];
    float* out = (float*)d_out;

    cudaFuncSetAttribute(k_L_mma, cudaFuncAttributeMaxDynamicSharedMemorySize, LSM_LAST);

    ushortx *hxHa,*hxLa,*hxHb,*hxLb;
    cudaGetSymbolAddress((void**)&hxHa, g_hxHIa);
    cudaGetSymbolAddress((void**)&hxLa, g_hxLOa);
    cudaGetSymbolAddress((void**)&hxHb, g_hxHIb);
    cudaGetSymbolAddress((void**)&hxLb, g_hxLOb);

    k_prep_all<<<PB_TOTAL, 256>>>(bases, W1, Do, Di, product, A, Bm, x,
                                  W_conv, W0, b0, b_conv);
    k_wbTP<<<dim3(NXS/32, MODE/32), dim3(32,8)>>>(wbases);

    // ---- layer 0 ----
    k_T<<<dim3(BSZ, T_SPLITS), MODE>>>(wbases);
    k_xh0<<<BSZ, 256>>>(W0, b0);
    k_xh1_mma<<<dim3(BSZ, NJ), 256>>>();
    k_WrTWc<<<272, 256>>>(W_sp, W_conv, 0, 0);
    k_y_mma<<<dim3(BSZ, Y_SPLITS), 256>>>();
    k_reduce_y<<<(BSZ*DIMC*MODE)/256, 256>>>();
    k_L_mma<<<dim3(BSZ, NXS/128), 256, LSM_MID>>>(hxHa, hxLa, hxHa, hxLa,
                                                  nullptr,
                                                  b1, W2, b2, out, 1, 0);
    // ---- layers 1,2 ----
    const ushortx *hxH = hxHa, *hxL = hxLa;
    ushortx *hxHo = hxHb, *hxLo = hxLb;
    for (int li = 1; li < N_LAYERS; li++){
        int last = (li == N_LAYERS-1) ? 1 : 0;
        k_xh_mma<<<dim3((BSZ*DIMC)/128, XH_SPLITS), 256>>>(hxH, hxL);
        k_reduce_xh<<<(BSZ*DIMC*MODE)/256, 256>>>();
        k_xh1_mma<<<dim3(BSZ, NJ), 256>>>();
        k_WrTWc<<<272, 256>>>(W_sp, W_conv, li, 1);
        k_y_mma<<<dim3(BSZ, Y_SPLITS), 256>>>();
        k_reduce_y<<<(BSZ*DIMC*MODE)/256, 256>>>();
        k_L_mma<<<dim3(BSZ, NXS/128), 256, last ? LSM_LAST : LSM_MID>>>(
                                             hxH, hxL, hxHo, hxLo,
                                             &b_conv[(size_t)li*DIMC],
                                             b1, W2, b2, out, 0, last);
        const ushortx* t3 = hxH; hxH = hxHo; hxHo = (ushortx*)t3;
        const ushortx* t4 = hxL; hxL = hxLo; hxLo = (ushortx*)t4;
    }
}

// round 17
// speedup vs baseline: 1.1125x; 1.0180x over previous
#include <cuda_runtime.h>
#include <cuda_bf16.h>
#include <math.h>
#include <stdint.h>

#define BSZ 32
#define NXS 16384
#define IN_DIM 3
#define DIMC 64
#define NJ 16
#define MODE 128
#define RANKR 4
#define FCD 128
#define N_LAYERS 3
#define XH_SPLITS 16
#define Y_SPLITS 8
#define T_SPLITS 8

typedef unsigned short ushortx;

__device__ ushortx g_hxHIa[(size_t)BSZ*NXS*DIMC];
__device__ ushortx g_hxLOa[(size_t)BSZ*NXS*DIMC];
__device__ ushortx g_hxHIb[(size_t)BSZ*NXS*DIMC];
__device__ ushortx g_hxLOb[(size_t)BSZ*NXS*DIMC];
__device__ ushortx g_wbTHI[(size_t)MODE*NXS];
__device__ ushortx g_wbTLO[(size_t)MODE*NXS];
__device__ ushortx g_basesHI[(size_t)NXS*MODE];
__device__ ushortx g_basesLO[(size_t)NXS*MODE];
__device__ ushortx g_W1THI[FCD*DIMC];
__device__ ushortx g_W1TLO[FCD*DIMC];
__device__ ushortx g_HjHI[NJ*MODE*MODE];
__device__ ushortx g_HjLO[NJ*MODE*MODE];
__device__ ushortx g_xhHI[BSZ*DIMC*MODE];
__device__ ushortx g_xhLO[BSZ*DIMC*MODE];
__device__ ushortx g_x1THI[(size_t)BSZ*MODE*(DIMC*NJ)];
__device__ ushortx g_x1TLO[(size_t)BSZ*MODE*(DIMC*NJ)];
__device__ ushortx g_WrTTHI[DIMC*DIMC*NJ];
__device__ ushortx g_WrTTLO[DIMC*DIMC*NJ];
__device__ ushortx g_yHI[BSZ*DIMC*MODE];
__device__ ushortx g_yLO[BSZ*DIMC*MODE];
__device__ ushortx g_WcHI[DIMC*DIMC];
__device__ ushortx g_WcLO[DIMC*DIMC];
__device__ float g_xT[BSZ*IN_DIM*NXS];
__device__ float g_xhp[XH_SPLITS*BSZ*DIMC*MODE];
__device__ float g_yp [Y_SPLITS*BSZ*DIMC*MODE];
__device__ float g_Tp [T_SPLITS*BSZ*4*MODE];
__device__ float g_Wc0T[IN_DIM*DIMC];
__device__ float g_bias0[DIMC];

__device__ __forceinline__ float gelu_f(float v){
    return 0.5f * v * (1.0f + erff(v * 0.70710678118654752440f));
}
__device__ __forceinline__ void split2(float x, ushortx& hi, ushortx& lo){
    __nv_bfloat16 h = __float2bfloat16(x);
    hi = __bfloat16_as_ushort(h);
    lo = __bfloat16_as_ushort(__float2bfloat16(x - __bfloat162float(h)));
}
__device__ __forceinline__ unsigned pk_split(float x){
    ushortx hi, lo; split2(x, hi, lo);
    return ((unsigned)hi << 16) | (unsigned)lo;
}
#define MMA(c,a,b) asm volatile( \
    "mma.sync.aligned.m16n8k16.row.col.f32.bf16.bf16.f32 " \
    "{%0,%1,%2,%3}, {%4,%5,%6,%7}, {%8,%9}, {%0,%1,%2,%3};" \
    : "+f"((c)[0]), "+f"((c)[1]), "+f"((c)[2]), "+f"((c)[3]) \
    : "r"((a)[0]), "r"((a)[1]), "r"((a)[2]), "r"((a)[3]), "r"((b)[0]), "r"((b)[1]))
#define LDSM4(f,addr) asm volatile( \
    "ldmatrix.sync.aligned.m8n8.x4.shared.b16 {%0,%1,%2,%3}, [%4];" \
    : "=r"((f)[0]), "=r"((f)[1]), "=r"((f)[2]), "=r"((f)[3]) : "r"(addr))
#define LDSM4T(f,addr) asm volatile( \
    "ldmatrix.sync.aligned.m8n8.x4.trans.shared.b16 {%0,%1,%2,%3}, [%4];" \
    : "=r"((f)[0]), "=r"((f)[1]), "=r"((f)[2]), "=r"((f)[3]) : "r"(addr))
#define CPA(dst,src) asm volatile("cp.async.cg.shared.global [%0], [%1], 16;" :: "r"(dst), "l"(src))
#define CPC() asm volatile("cp.async.commit_group;" ::: "memory")
#define CPW1() asm volatile("cp.async.wait_group 1;" ::: "memory")
#define CPW0() asm volatile("cp.async.wait_group 0;" ::: "memory")

// ============ fused prep: basesP | W1TP | buildH | xT | prep0 ============
#define PB_BASES 8192
#define PB_W1    (PB_BASES + 32)
#define PB_H     (PB_W1 + 1024)
#define PB_XT    (PB_H + 6144)
#define PB_TOTAL (PB_XT + 1)
__global__ void k_prep_all(const float* __restrict__ bases, const float* __restrict__ W1,
                           const float* __restrict__ Do, const float* __restrict__ Di,
                           const float* __restrict__ pr, const float* __restrict__ A,
                           const float* __restrict__ Bm, const float* __restrict__ x,
                           const float* __restrict__ W_conv, const float* __restrict__ W0,
                           const float* __restrict__ b0, const float* __restrict__ b_conv){
    int gb = blockIdx.x, tid = threadIdx.x;
    if (gb < PB_BASES){
        int i = gb*256 + tid;
        split2(bases[i], g_basesHI[i], g_basesLO[i]);
    } else if (gb < PB_W1){
        int i = (gb - PB_BASES)*256 + tid;
        int f = i >> 6, c = i & 63;
        split2(W1[c*FCD + f], g_W1THI[i], g_W1TLO[i]);
    } else if (gb < PB_H){
        int i = (gb - PB_W1)*256 + tid;
        int j = i >> 14, r = i & 16383;
        int k = r >> 7, l = r & 127;
        float s = Do[j*MODE + k] * Di[j*MODE + l] * pr[k*MODE + l];
        #pragma unroll
        for (int rr = 0; rr < RANKR; rr++)
            s += A[(j*RANKR + rr)*MODE + k] * Bm[(j*RANKR + rr)*MODE + l];
        split2(s, g_HjHI[i], g_HjLO[i]);
    } else if (gb < PB_XT){
        int i = (gb - PB_H)*256 + tid;
        int d = i % 3, t = i / 3;
        g_xT[((size_t)(t >> 14)*IN_DIM + d)*NXS + (t & (NXS-1))] = x[i];
    } else {
        if (tid >= DIMC) return;
        int o = tid;
        float w0s = 0.f, w1s = 0.f, w2s = 0.f, bb = b_conv[o];
        for (int c = 0; c < DIMC; c++){
            float wc = W_conv[o*DIMC + c];
            w0s += wc*W0[c]; w1s += wc*W0[DIMC+c]; w2s += wc*W0[2*DIMC+c];
            bb  += wc*b0[c];
        }
        g_Wc0T[o] = w0s; g_Wc0T[64+o] = w1s; g_Wc0T[128+o] = w2s; g_bias0[o] = bb;
    }
}
__global__ void k_wbTP(const float* __restrict__ wb){
    __shared__ float t[32][33];
    int x0 = blockIdx.x * 32, k0 = blockIdx.y * 32;
    for (int i = threadIdx.y; i < 32; i += 8)
        t[i][threadIdx.x] = wb[(size_t)(x0 + i)*MODE + k0 + threadIdx.x];
    __syncthreads();
    for (int i = threadIdx.y; i < 32; i += 8){
        size_t o = (size_t)(k0 + i)*NXS + x0 + threadIdx.x;
        split2(t[threadIdx.x][i], g_wbTHI[o], g_wbTLO[o]);
    }
}
__global__ void k_T(const float* __restrict__ wbases){
    int b = blockIdx.x, s = blockIdx.y;
    int x0 = s * (NXS / T_SPLITS);
    int k = threadIdx.x;
    __shared__ float xs[3][128];
    float a0=0.f, a1=0.f, a2=0.f, a3=0.f;
    for (int xt = 0; xt < (NXS/T_SPLITS)/128; xt++){
        __syncthreads();
        xs[0][k] = g_xT[((size_t)b*IN_DIM + 0)*NXS + x0 + xt*128 + k];
        xs[1][k] = g_xT[((size_t)b*IN_DIM + 1)*NXS + x0 + xt*128 + k];
        xs[2][k] = g_xT[((size_t)b*IN_DIM + 2)*NXS + x0 + xt*128 + k];
        __syncthreads();
        #pragma unroll 8
        for (int xi = 0; xi < 128; xi++){
            float w = wbases[(size_t)(x0 + xt*128 + xi)*MODE + k];
            a0 += xs[0][xi]*w; a1 += xs[1][xi]*w; a2 += xs[2][xi]*w; a3 += w;
        }
    }
    size_t base = (((size_t)s*BSZ + b)*4)*MODE + k;
    g_Tp[base] = a0; g_Tp[base+MODE] = a1; g_Tp[base+2*MODE] = a2; g_Tp[base+3*MODE] = a3;
}
__global__ void k_xh0(const float* __restrict__ W0, const float* __restrict__ b0){
    int b = blockIdx.x;
    __shared__ float Ts[4][128];
    int tid = threadIdx.x;
    for (int e = tid; e < 4*MODE; e += 256){
        int d = e >> 7, k = e & 127;
        float s = 0.f;
        #pragma unroll
        for (int s8 = 0; s8 < T_SPLITS; s8++)
            s += g_Tp[(((size_t)s8*BSZ + b)*4 + d)*MODE + k];
        Ts[d][k] = s;
    }
    __syncthreads();
    for (int o = tid; o < DIMC*MODE; o += 256){
        int c = o >> 7, k = o & 127;
        float v = W0[c]*Ts[0][k] + W0[DIMC+c]*Ts[1][k] + W0[2*DIMC+c]*Ts[2][k] + b0[c]*Ts[3][k];
        size_t idx = (size_t)b*DIMC*MODE + o;
        split2(v, g_xhHI[idx], g_xhLO[idx]);
    }
}

// ===== GEMM1 (R12 pipeline: CPW1) =====
__global__ void __launch_bounds__(256) k_xh_mma(const ushortx* __restrict__ hxHI,
                                                const ushortx* __restrict__ hxLO){
    __shared__ __align__(16) unsigned smA[2][2][16][68];
    __shared__ __align__(16) unsigned smB[2][2][128][12];
    const int NIT = (NXS/XH_SPLITS)/16;
    int tid = threadIdx.x, lane = tid & 31, wid = tid >> 5;
    int wm = wid >> 2, wn = wid & 3, g = lane >> 2, t = lane & 3;
    int m0 = blockIdx.x * 128, b0 = blockIdx.x * 2;
    int k0 = blockIdx.y * (NXS / XH_SPLITS);
    int xr = tid >> 4, bl = (tid >> 3) & 1, cq = tid & 7;
    const ushortx* sAh = hxHI + ((size_t)(b0+bl)*NXS + k0 + xr)*DIMC + cq*8;
    const ushortx* sAl = hxLO + ((size_t)(b0+bl)*NXS + k0 + xr)*DIMC + cq*8;
    unsigned dAh = (unsigned)__cvta_generic_to_shared(&smA[0][0][xr][bl*32 + cq*4]);
    unsigned dAl = (unsigned)__cvta_generic_to_shared(&smA[1][0][xr][bl*32 + cq*4]);
    int rB = tid >> 1, chB = tid & 1;
    const ushortx* sBh = g_wbTHI + (size_t)rB*NXS + k0 + chB*8;
    const ushortx* sBl = g_wbTLO + (size_t)rB*NXS + k0 + chB*8;
    unsigned dBh = (unsigned)__cvta_generic_to_shared(&smB[0][0][rB][chB*4]);
    unsigned dBl = (unsigned)__cvta_generic_to_shared(&smB[1][0][rB][chB*4]);
    unsigned bAh = (unsigned)__cvta_generic_to_shared(&smA[0][0][0][0]);
    unsigned bAl = (unsigned)__cvta_generic_to_shared(&smA[1][0][0][0]);
    unsigned bBh = (unsigned)__cvta_generic_to_shared(&smB[0][0][0][0]);
    unsigned bBl = (unsigned)__cvta_generic_to_shared(&smB[1][0][0][0]);
    const unsigned ABUFO = 16*68*4, BBUFO = 128*48;
    unsigned loffT = ((lane & 7) + (lane >> 4)*8)*272 + ((lane >> 3) & 1)*16;
    unsigned loff  = (lane & 15)*48 + (lane >> 4)*16;
    float c[4][4][4] = {};
    CPA(dAh, sAh); CPA(dAl, sAl); CPA(dBh, sBh); CPA(dBl, sBl);
    CPC();
    for (int it = 0; it < NIT; it++){
        int cur = it & 1, nxt = cur ^ 1;
        if (it + 1 < NIT){
            CPA(dAh + nxt*ABUFO, sAh + (size_t)(it+1)*16*DIMC);
            CPA(dAl + nxt*ABUFO, sAl + (size_t)(it+1)*16*DIMC);
            CPA(dBh + nxt*BBUFO, sBh + (it+1)*16);
            CPA(dBl + nxt*BBUFO, sBl + (it+1)*16);
            CPC(); CPW1();
        } else CPW0();
        __syncthreads();
        unsigned Ah[4][4], Al[4][4], Bh[2][4], Bl[2][4];
        #pragma unroll
        for (int tm = 0; tm < 4; tm++){
            LDSM4T(Ah[tm], bAh + cur*ABUFO + loffT + (wm*64 + tm*16)*2);
            LDSM4T(Al[tm], bAl + cur*ABUFO + loffT + (wm*64 + tm*16)*2);
        }
        #pragma unroll
        for (int p = 0; p < 2; p++){
            LDSM4(Bh[p], bBh + cur*BBUFO + loff + (wn*32 + p*16)*48);
            LDSM4(Bl[p], bBl + cur*BBUFO + loff + (wn*32 + p*16)*48);
        }
        #pragma unroll
        for (int tm = 0; tm < 4; tm++)
            #pragma unroll
            for (int tn = 0; tn < 4; tn++){
                int p = tn >> 1, e = tn & 1;
                unsigned bh[2] = {Bh[p][e], Bh[p][e+2]};
                unsigned bl[2] = {Bl[p][e], Bl[p][e+2]};
                MMA(c[tm][tn], Ah[tm], bh);
                MMA(c[tm][tn], Al[tm], bh);
                MMA(c[tm][tn], Ah[tm], bl);
            }
        __syncthreads();
    }
    float* dst = &g_xhp[(size_t)blockIdx.y*(BSZ*DIMC*MODE)];
    #pragma unroll
    for (int tm = 0; tm < 4; tm++)
        #pragma unroll
        for (int tn = 0; tn < 4; tn++){
            int m = m0 + wm*64 + tm*16 + g;
            int n = wn*32 + tn*8 + t*2;
            *(float2*)&dst[(size_t)m*MODE + n]     = make_float2(c[tm][tn][0], c[tm][tn][1]);
            *(float2*)&dst[(size_t)(m+8)*MODE + n] = make_float2(c[tm][tn][2], c[tm][tn][3]);
        }
}
__global__ void k_reduce_xh(){
    int i = blockIdx.x * 256 + threadIdx.x;
    float s = 0.f;
    #pragma unroll
    for (int k = 0; k < XH_SPLITS; k++) s += g_xhp[(size_t)k*(BSZ*DIMC*MODE) + i];
    split2(s, g_xhHI[i], g_xhLO[i]);
}

// ===== xh1 (mma, R12 pipeline) =====
__global__ void __launch_bounds__(256) k_xh1_mma(){
    __shared__ __align__(16) unsigned smA[2][2][64][12];
    __shared__ __align__(16) unsigned smB[2][2][128][12];
    int tid = threadIdx.x, lane = tid & 31, wid = tid >> 5;
    int wm = wid >> 2, wn = wid & 3, g = lane >> 2, t = lane & 3;
    int b = blockIdx.x, j = blockIdx.y;
    unsigned loff = (lane & 15)*48 + (lane >> 4)*16;
    int aA = tid >> 7, rA = (tid >> 1) & 63, hA = tid & 1;
    const ushortx* srcA = (aA ? g_xhLO : g_xhHI) + ((size_t)b*DIMC + rA)*MODE + hA*8;
    unsigned dA = (unsigned)__cvta_generic_to_shared(&smA[aA][0][rA][hA*4]);
    unsigned bAh = (unsigned)__cvta_generic_to_shared(&smA[0][0][0][0]);
    unsigned bAl = (unsigned)__cvta_generic_to_shared(&smA[1][0][0][0]);
    unsigned bBh = (unsigned)__cvta_generic_to_shared(&smB[0][0][0][0]);
    unsigned bBl = (unsigned)__cvta_generic_to_shared(&smB[1][0][0][0]);
    const unsigned ABUFO = 64*12*4, BBUFO = 128*12*4;
    float c[2][4][4] = {};
    CPA(dA, srcA);
    #pragma unroll
    for (int rep = 0; rep < 2; rep++){
        int cid = tid + rep*256;
        int aB = cid >> 8, rBx = (cid >> 1) & 127, hB = cid & 1;
        const ushortx* srcB = (aB ? g_HjLO : g_HjHI) + ((size_t)j*MODE + rBx)*MODE + hB*8;
        CPA((unsigned)__cvta_generic_to_shared(&smB[aB][0][rBx][hB*4]), srcB);
    }
    CPC();
    for (int ks = 0; ks < 8; ks++){
        int cur = ks & 1, nxt = cur ^ 1;
        if (ks + 1 < 8){
            CPA(dA + nxt*ABUFO, srcA + (ks+1)*16);
            #pragma unroll
            for (int rep = 0; rep < 2; rep++){
                int cid = tid + rep*256;
                int aB = cid >> 8, rBx = (cid >> 1) & 127, hB = cid & 1;
                const ushortx* srcB = (aB ? g_HjLO : g_HjHI) + ((size_t)j*MODE + rBx)*MODE + hB*8;
                CPA((unsigned)__cvta_generic_to_shared(&smB[aB][0][rBx][hB*4]) + nxt*BBUFO,
                    srcB + (ks+1)*16);
            }
            CPC(); CPW1();
        } else CPW0();
        __syncthreads();
        unsigned offA = cur*ABUFO + loff, offB = cur*BBUFO + loff;
        unsigned Ah[2][4], Al[2][4], Bh[2][4], Bl[2][4];
        #pragma unroll
        for (int tm = 0; tm < 2; tm++){
            LDSM4(Ah[tm], bAh + offA + (wm*32 + tm*16)*48);
            LDSM4(Al[tm], bAl + offA + (wm*32 + tm*16)*48);
        }
        #pragma unroll
        for (int p = 0; p < 2; p++){
            LDSM4(Bh[p], bBh + offB + (wn*32 + p*16)*48);
            LDSM4(Bl[p], bBl + offB + (wn*32 + p*16)*48);
        }
        #pragma unroll
        for (int tm = 0; tm < 2; tm++)
            #pragma unroll
            for (int tn = 0; tn < 4; tn++){
                int p = tn >> 1, e = tn & 1;
                unsigned bh[2] = {Bh[p][e], Bh[p][e+2]};
                unsigned bl[2] = {Bl[p][e], Bl[p][e+2]};
                MMA(c[tm][tn], Ah[tm], bh);
                MMA(c[tm][tn], Al[tm], bh);
                MMA(c[tm][tn], Ah[tm], bl);
            }
        __syncthreads();
    }
    #pragma unroll
    for (int tm = 0; tm < 2; tm++)
        #pragma unroll
        for (int tn = 0; tn < 4; tn++){
            int m = wm*32 + tm*16 + g;
            int n = wn*32 + tn*8 + t*2;
            #pragma unroll
            for (int e = 0; e < 4; e++){
                int mm = m + (e >> 1)*8, nn = n + (e & 1);
                size_t o = ((size_t)b*MODE + nn)*(DIMC*NJ) + j*64 + mm;
                split2(c[tm][tn][e], g_x1THI[o], g_x1TLO[o]);
            }
        }
}
__global__ void k_WrTWc(const float* __restrict__ W_sp, const float* __restrict__ W_conv,
                        int li, int do_wc){
    int gb = blockIdx.x;
    if (gb < 256){
        int idx = gb * 256 + threadIdx.x;
        int p = idx & 1023, o = idx >> 10;
        int j = p >> 6, cc = p & 63;
        float v = W_sp[(((size_t)li*DIMC + cc)*DIMC + o)*NJ + j];
        split2(v, g_WrTTHI[idx], g_WrTTLO[idx]);
    } else if (do_wc){
        int i = (gb - 256) * 256 + threadIdx.x;
        split2(W_conv[(size_t)li*DIMC*DIMC + i], g_WcHI[i], g_WcLO[i]);
    }
}
// y split-K: KCH = 1024/Y_SPLITS per split
__global__ void __launch_bounds__(256) k_y_mma(){
    __shared__ __align__(16) unsigned smA[2][2][64][12];
    __shared__ __align__(16) unsigned smB[2][2][128][12];
    const int KCH = (DIMC*NJ)/Y_SPLITS;
    const int NKS = KCH/16;
    int tid = threadIdx.x, lane = tid & 31, wid = tid >> 5;
    int wm = wid >> 2, wn = wid & 3, g = lane >> 2, t = lane & 3;
    int b = blockIdx.x, sp = blockIdx.y;
    int p0 = sp * KCH;
    unsigned loff = (lane & 15)*48 + (lane >> 4)*16;
    int aA = tid >> 7, rA = (tid >> 1) & 63, hA = tid & 1;
    const ushortx* srcA = (aA ? g_WrTTLO : g_WrTTHI) + (size_t)rA*(DIMC*NJ) + p0 + hA*8;
    unsigned dA = (unsigned)__cvta_generic_to_shared(&smA[aA][0][rA][hA*4]);
    unsigned bAh = (unsigned)__cvta_generic_to_shared(&smA[0][0][0][0]);
    unsigned bAl = (unsigned)__cvta_generic_to_shared(&smA[1][0][0][0]);
    unsigned bBh = (unsigned)__cvta_generic_to_shared(&smB[0][0][0][0]);
    unsigned bBl = (unsigned)__cvta_generic_to_shared(&smB[1][0][0][0]);
    const unsigned ABUFO = 64*12*4, BBUFO = 128*12*4;
    float c[2][4][4] = {};
    CPA(dA, srcA);
    #pragma unroll
    for (int rep = 0; rep < 2; rep++){
        int cid = tid + rep*256;
        int aB = cid >> 8, rBx = (cid >> 1) & 127, hB = cid & 1;
        const ushortx* srcB = (aB ? g_x1TLO : g_x1THI) + ((size_t)b*MODE + rBx)*(DIMC*NJ) + p0 + hB*8;
        CPA((unsigned)__cvta_generic_to_shared(&smB[aB][0][rBx][hB*4]), srcB);
    }
    CPC();
    for (int ks = 0; ks < NKS; ks++){
        int cur = ks & 1, nxt = cur ^ 1;
        if (ks + 1 < NKS){
            CPA(dA + nxt*ABUFO, srcA + (ks+1)*16);
            #pragma unroll
            for (int rep = 0; rep < 2; rep++){
                int cid = tid + rep*256;
                int aB = cid >> 8, rBx = (cid >> 1) & 127, hB = cid & 1;
                const ushortx* srcB = (aB ? g_x1TLO : g_x1THI) + ((size_t)b*MODE + rBx)*(DIMC*NJ) + p0 + hB*8;
                CPA((unsigned)__cvta_generic_to_shared(&smB[aB][0][rBx][hB*4]) + nxt*BBUFO,
                    srcB + (ks+1)*16);
            }
            CPC(); CPW1();
        } else CPW0();
        __syncthreads();
        unsigned offA = cur*ABUFO + loff, offB = cur*BBUFO + loff;
        unsigned Ah[2][4], Al[2][4], Bh[2][4], Bl[2][4];
        #pragma unroll
        for (int tm = 0; tm < 2; tm++){
            LDSM4(Ah[tm], bAh + offA + (wm*32 + tm*16)*48);
            LDSM4(Al[tm], bAl + offA + (wm*32 + tm*16)*48);
        }
        #pragma unroll
        for (int p = 0; p < 2; p++){
            LDSM4(Bh[p], bBh + offB + (wn*32 + p*16)*48);
            LDSM4(Bl[p], bBl + offB + (wn*32 + p*16)*48);
        }
        #pragma unroll
        for (int tm = 0; tm < 2; tm++)
            #pragma unroll
            for (int tn = 0; tn < 4; tn++){
                int p = tn >> 1, e = tn & 1;
                unsigned bh[2] = {Bh[p][e], Bh[p][e+2]};
                unsigned bl[2] = {Bl[p][e], Bl[p][e+2]};
                MMA(c[tm][tn], Ah[tm], bh);
                MMA(c[tm][tn], Al[tm], bh);
                MMA(c[tm][tn], Ah[tm], bl);
            }
        __syncthreads();
    }
    float* dst = &g_yp[(size_t)sp*(BSZ*DIMC*MODE)];
    #pragma unroll
    for (int tm = 0; tm < 2; tm++)
        #pragma unroll
        for (int tn = 0; tn < 4; tn++){
            int m = wm*32 + tm*16 + g;
            int n = wn*32 + tn*8 + t*2;
            *(float2*)&dst[((size_t)b*DIMC + m)*MODE + n]     = make_float2(c[tm][tn][0], c[tm][tn][1]);
            *(float2*)&dst[((size_t)b*DIMC + m + 8)*MODE + n] = make_float2(c[tm][tn][2], c[tm][tn][3]);
        }
}
__global__ void k_reduce_y(){
    int i = blockIdx.x * 256 + threadIdx.x;
    float s = 0.f;
    #pragma unroll
    for (int k = 0; k < Y_SPLITS; k++) s += g_yp[(size_t)k*(BSZ*DIMC*MODE) + i];
    split2(s, g_yHI[i], g_yLO[i]);
}

// ===== GEMM2 + tensorized fc1 (unchanged from R16 best) =====
#define CSW 132
#define AHI_OFF 0
#define ALO_OFF 12288
#define BHI_OFF 24576
#define BLO_OFF 30720
#define ABUF 6144
#define BBUF 3072
#define FAHI 36864
#define FALO 43008
#define FBHI 49152
#define FBLO 55296
#define LSM_LAST 61440
#define LSM_MID  36864
__global__ void __launch_bounds__(256) k_L_mma(
    const ushortx* __restrict__ hxHI, const ushortx* __restrict__ hxLO,
    ushortx* __restrict__ hxoHI, ushortx* __restrict__ hxoLO,
    const float* __restrict__ biasv,
    const float* __restrict__ b1, const float* __restrict__ W2,
    const float* __restrict__ b2,
    float* __restrict__ out, int tail3, int is_last)
{
    extern __shared__ __align__(16) char pool[];
    float (*Csm)[CSW]  = (float(*)[CSW])pool;
    unsigned (*CsmU)[CSW] = (unsigned(*)[CSW])pool;
    int tid = threadIdx.x, lane = tid & 31, wid = tid >> 5;
    int wm = wid >> 2, wn = wid & 3, g = lane >> 2, t = lane & 3;
    int wmA = wid >> 1, wnA = wid & 1;
    int b = blockIdx.x;
    int x0 = blockIdx.y * 128;
    int row = tid >> 1, ch = tid & 1;
    int nch = tail3 ? 8 : 12;
    unsigned sbase = (unsigned)__cvta_generic_to_shared(pool);
    unsigned dAhi = sbase + AHI_OFF + row*48 + ch*16;
    unsigned dAlo = dAhi + (ALO_OFF - AHI_OFF);
    unsigned bAhi = sbase + AHI_OFF, bAlo = sbase + ALO_OFF;
    unsigned bBhi = sbase + BHI_OFF, bBlo = sbase + BLO_OFF;
    int bhalf = tid >> 7, bo = (tid >> 1) & 63, bh = tid & 1;
    const ushortx* sBy = (bhalf ? g_yLO : g_yHI) + ((size_t)b*DIMC + bo)*MODE + bh*8;
    const ushortx* sBw = (bhalf ? g_WcLO : g_WcHI) + (size_t)bo*DIMC + bh*8;
    unsigned dB = sbase + (bhalf ? BLO_OFF : BHI_OFF) + bo*48 + bh*16;
    unsigned loff = (lane & 15)*48 + (lane >> 4)*16;
    float c[2][4][4] = {};
    CPA(dAhi, g_basesHI + (size_t)(x0+row)*MODE + ch*8);
    CPA(dAlo, g_basesLO + (size_t)(x0+row)*MODE + ch*8);
    CPA(dB, sBy);
    CPC();
    for (int chn = 0; chn < nch; chn++){
        int cur = chn & 1, nxt = cur ^ 1;
        if (chn + 1 < nch){
            int cn = chn + 1;
            if (cn < 8){
                CPA(dAhi + nxt*ABUF, g_basesHI + (size_t)(x0+row)*MODE + cn*16 + ch*8);
                CPA(dAlo + nxt*ABUF, g_basesLO + (size_t)(x0+row)*MODE + cn*16 + ch*8);
                CPA(dB + nxt*BBUF, sBy + cn*16);
            } else {
                CPA(dAhi + nxt*ABUF, hxHI + ((size_t)b*NXS + x0 + row)*DIMC + (cn-8)*16 + ch*8);
                CPA(dAlo + nxt*ABUF, hxLO + ((size_t)b*NXS + x0 + row)*DIMC + (cn-8)*16 + ch*8);
                CPA(dB + nxt*BBUF, sBw + (cn-8)*16);
            }
            CPC(); CPW1();
        } else CPW0();
        __syncthreads();
        unsigned offA = cur*ABUF + loff;
        unsigned offB = cur*BBUF + loff;
        unsigned Ah[2][4], Al[2][4], Bh[2][4], Bl[2][4];
        #pragma unroll
        for (int tm = 0; tm < 2; tm++){
            LDSM4(Ah[tm], bAhi + offA + (wmA*32 + tm*16)*48);
            LDSM4(Al[tm], bAlo + offA + (wmA*32 + tm*16)*48);
        }
        #pragma unroll
        for (int p = 0; p < 2; p++){
            LDSM4(Bh[p], bBhi + offB + (wnA*32 + p*16)*48);
            LDSM4(Bl[p], bBlo + offB + (wnA*32 + p*16)*48);
        }
        #pragma unroll
        for (int tm = 0; tm < 2; tm++)
            #pragma unroll
            for (int tn = 0; tn < 4; tn++){
                int p = tn >> 1, e = tn & 1;
                unsigned bhv[2] = {Bh[p][e], Bh[p][e+2]};
                unsigned blv[2] = {Bl[p][e], Bl[p][e+2]};
                MMA(c[tm][tn], Ah[tm], bhv);
                MMA(c[tm][tn], Al[tm], bhv);
                MMA(c[tm][tn], Ah[tm], blv);
            }
        __syncthreads();
    }
    #pragma unroll
    for (int tm = 0; tm < 2; tm++)
        #pragma unroll
        for (int tn = 0; tn < 4; tn++){
            int xr = wmA*32 + tm*16 + g;
            int oc = wnA*32 + tn*8 + t*2;
            Csm[oc][xr]     = c[tm][tn][0]; Csm[oc+1][xr]   = c[tm][tn][1];
            Csm[oc][xr+8]   = c[tm][tn][2]; Csm[oc+1][xr+8] = c[tm][tn][3];
        }
    __syncthreads();
    {
        int o = tid >> 2;
        float bias = tail3 ? g_bias0[o] : biasv[o];
        float w0 = 0.f, w1 = 0.f, w2c = 0.f;
        if (tail3){ w0 = g_Wc0T[o]; w1 = g_Wc0T[64+o]; w2c = g_Wc0T[128+o]; }
        #pragma unroll 4
        for (int j = 0; j < 32; j++){
            int xr = (tid & 3)*32 + j;
            float v = Csm[o][xr] + bias;
            if (tail3){
                int gx = x0 + xr;
                v += g_xT[((size_t)b*IN_DIM + 0)*NXS + gx]*w0
                   + g_xT[((size_t)b*IN_DIM + 1)*NXS + gx]*w1
                   + g_xT[((size_t)b*IN_DIM + 2)*NXS + gx]*w2c;
            }
            if (!is_last) CsmU[o][xr] = pk_split(gelu_f(v));
            else          Csm[o][xr] = v;
        }
    }
    __syncthreads();
    if (!is_last){
        for (int i = tid; i < 128*32; i += 256){
            int xx = i >> 5, cp = i & 31;
            unsigned u0 = CsmU[2*cp][xx], u1 = CsmU[2*cp+1][xx];
            unsigned hi = (u0 >> 16) | (u1 & 0xFFFF0000u);
            unsigned lo = (u0 & 0xFFFFu) | (u1 << 16);
            size_t base = ((size_t)b*NXS + x0 + xx)*DIMC;
            ((unsigned*)(hxoHI + base))[cp] = hi;
            ((unsigned*)(hxoLO + base))[cp] = lo;
        }
        return;
    }
    float c2[4][4][4] = {};
    int hh_ = tid & 1, xr_ = tid >> 1;
    for (int ks = 0; ks < 4; ks++){
        CPA(sbase + FBHI + row*48 + hh_*16, g_W1THI + row*64 + ks*16 + hh_*8);
        CPA(sbase + FBLO + row*48 + hh_*16, g_W1TLO + row*64 + ks*16 + hh_*8);
        CPC();
        {
            unsigned uh[4], ul[4];
            #pragma unroll
            for (int j = 0; j < 4; j++){
                ushortx h0,l0,h1,l1;
                split2(Csm[ks*16 + hh_*8 + 2*j][xr_], h0, l0);
                split2(Csm[ks*16 + hh_*8 + 2*j+1][xr_], h1, l1);
                uh[j] = (unsigned)h0 | ((unsigned)h1 << 16);
                ul[j] = (unsigned)l0 | ((unsigned)l1 << 16);
            }
            *(uint4*)(pool + FAHI + xr_*48 + hh_*16) = make_uint4(uh[0],uh[1],uh[2],uh[3]);
            *(uint4*)(pool + FALO + xr_*48 + hh_*16) = make_uint4(ul[0],ul[1],ul[2],ul[3]);
        }
        CPW0();
        __syncthreads();
        unsigned Ah[4][4], Al[4][4], Bh[2][4], Bl[2][4];
        #pragma unroll
        for (int tm = 0; tm < 4; tm++){
            LDSM4(Ah[tm], sbase + FAHI + loff + (wm*64 + tm*16)*48);
            LDSM4(Al[tm], sbase + FALO + loff + (wm*64 + tm*16)*48);
        }
        #pragma unroll
        for (int p = 0; p < 2; p++){
            LDSM4(Bh[p], sbase + FBHI + loff + (wn*32 + p*16)*48);
            LDSM4(Bl[p], sbase + FBLO + loff + (wn*32 + p*16)*48);
        }
        #pragma unroll
        for (int tm = 0; tm < 4; tm++)
            #pragma unroll
            for (int tn = 0; tn < 4; tn++){
                int p = tn >> 1, e = tn & 1;
                unsigned bh[2] = {Bh[p][e], Bh[p][e+2]};
                unsigned bl[2] = {Bl[p][e], Bl[p][e+2]};
                MMA(c2[tm][tn], Ah[tm], bh);
                MMA(c2[tm][tn], Al[tm], bh);
                MMA(c2[tm][tn], Ah[tm], bl);
            }
        __syncthreads();
    }
    float part[4][2] = {};
    #pragma unroll
    for (int tn = 0; tn < 4; tn++){
        int f0 = wn*32 + tn*8 + t*2;
        float b10 = b1[f0], b11 = b1[f0+1];
        float w20 = W2[f0], w21 = W2[f0+1];
        #pragma unroll
        for (int tm = 0; tm < 4; tm++){
            part[tm][0] += gelu_f(c2[tm][tn][0]+b10)*w20 + gelu_f(c2[tm][tn][1]+b11)*w21;
            part[tm][1] += gelu_f(c2[tm][tn][2]+b10)*w20 + gelu_f(c2[tm][tn][3]+b11)*w21;
        }
    }
    float (*red)[16] = (float(*)[16])(pool + FAHI);
    #pragma unroll
    for (int tm = 0; tm < 4; tm++){
        int xr0 = wm*64 + tm*16 + g;
        red[xr0][wn*4 + t]   = part[tm][0];
        red[xr0+8][wn*4 + t] = part[tm][1];
    }
    __syncthreads();
    if (tid < 128){
        float s = b2[0];
        #pragma unroll
        for (int k = 0; k < 16; k++) s += red[tid][k];
        out[(size_t)b*NXS + x0 + tid] = s;
    }
}

// ---------------------------------------------------------------------------
extern "C" void kernel_launch(void* const* d_in, const int* in_sizes, int n_in,
                              void* d_out, int out_size){
    (void)in_sizes; (void)n_in; (void)out_size;
    const float* x      = (const float*)d_in[0];
    const float* bases  = (const float*)d_in[1];
    const float* wbases = (const float*)d_in[2];
    const float* product= (const float*)d_in[3];
    const float* Do     = (const float*)d_in[4];
    const float* Di     = (const float*)d_in[5];
    const float* A      = (const float*)d_in[6];
    const float* Bm     = (const float*)d_in[7];
    const float* W_sp   = (const float*)d_in[8];
    const float* W_conv = (const float*)d_in[9];
    const float* b_conv = (const float*)d_in[10];
    const float* W0     = (const float*)d_in[11];
    const float* b0     = (const float*)d_in[12];
    const float* W1     = (const float*)d_in[13];
    const float* b1     = (const float*)d_in[14];
    const float* W2     = (const float*)d_in[15];
    const float* b2     = (const float*)d_in[16];
    float* out = (float*)d_out;

    cudaFuncSetAttribute(k_L_mma, cudaFuncAttributeMaxDynamicSharedMemorySize, LSM_LAST);

    ushortx *hxHa,*hxLa,*hxHb,*hxLb;
    cudaGetSymbolAddress((void**)&hxHa, g_hxHIa);
    cudaGetSymbolAddress((void**)&hxLa, g_hxLOa);
    cudaGetSymbolAddress((void**)&hxHb, g_hxHIb);
    cudaGetSymbolAddress((void**)&hxLb, g_hxLOb);

    k_prep_all<<<PB_TOTAL, 256>>>(bases, W1, Do, Di, product, A, Bm, x,
                                  W_conv, W0, b0, b_conv);
    k_wbTP<<<dim3(NXS/32, MODE/32), dim3(32,8)>>>(wbases);

    // ---- layer 0 ----
    k_T<<<dim3(BSZ, T_SPLITS), MODE>>>(wbases);
    k_xh0<<<BSZ, 256>>>(W0, b0);
    k_xh1_mma<<<dim3(BSZ, NJ), 256>>>();
    k_WrTWc<<<272, 256>>>(W_sp, W_conv, 0, 0);
    k_y_mma<<<dim3(BSZ, Y_SPLITS), 256>>>();
    k_reduce_y<<<(BSZ*DIMC*MODE)/256, 256>>>();
    k_L_mma<<<dim3(BSZ, NXS/128), 256, LSM_MID>>>(hxHa, hxLa, hxHa, hxLa,
                                                  nullptr,
                                                  b1, W2, b2, out, 1, 0);
    // ---- layers 1,2 ----
    const ushortx *hxH = hxHa, *hxL = hxLa;
    ushortx *hxHo = hxHb, *hxLo = hxLb;
    for (int li = 1; li < N_LAYERS; li++){
        int last = (li == N_LAYERS-1) ? 1 : 0;
        k_xh_mma<<<dim3((BSZ*DIMC)/128, XH_SPLITS), 256>>>(hxH, hxL);
        k_reduce_xh<<<(BSZ*DIMC*MODE)/256, 256>>>();
        k_xh1_mma<<<dim3(BSZ, NJ), 256>>>();
        k_WrTWc<<<272, 256>>>(W_sp, W_conv, li, 1);
        k_y_mma<<<dim3(BSZ, Y_SPLITS), 256>>>();
        k_reduce_y<<<(BSZ*DIMC*MODE)/256, 256>>>();
        k_L_mma<<<dim3(BSZ, NXS/128), 256, last ? LSM_LAST : LSM_MID>>>(
                                             hxH, hxL, hxHo, hxLo,
                                             &b_conv[(size_t)li*DIMC],
                                             b1, W2, b2, out, 0, last);
        const ushortx* t3 = hxH; hxH = hxHo; hxHo = (ushortx*)t3;
        const ushortx* t4 = hxL; hxL = hxLo; hxLo = (ushortx*)t4;
    }
}